// round 14
// baseline (speedup 1.0000x reference)
#include <cuda_runtime.h>
#include <cuda_fp16.h>
#include <math.h>
#include <stdint.h>

// Problem constants (fixed by the reference)
#define Nn   100000
#define Ee   1600000
#define INF  128
#define HIDF 64
#define NH   8
#define F1   512      // NH*HIDF
#define OUTF 64
#define ALPHA 0.2f
#define NB_SCAN ((Nn + 1023) / 1024)   // 98

// ---------------- device scratch (no allocations allowed) ----------------
__device__ __half g_x_h[(size_t)Nn * INF];        // 25.6 MB
__device__ __half g_xp_h[(size_t)Nn * INF];       // 25.6 MB
__device__ __half g_h1[(size_t)Nn * F1];          // 102.4 MB (~fits L2)
__device__ __half g_out1[(size_t)Nn * F1];        // 102.4 MB
__device__ __half g_h2h[Nn * OUTF];               // 12.8 MB (L2-resident)
__device__ __half g_W0h[INF * INF];
__device__ __half g_Wcat_h[INF * F1];             // repacked head weights (fp16)
__device__ __half g_Wend_h[F1 * OUTF];
__device__ float  g_ssrc1[Nn * NH];
__device__ float  g_sdst1[Nn * NH];
__device__ float  g_ssrc2[Nn];
__device__ float  g_sdst2[Nn];
__device__ int    g_counts[Nn];
__device__ int    g_fill[Nn];
__device__ int    g_rowptr[Nn + 1];
__device__ int    g_dst[Ee];
__device__ int    g_blksums[128];

// ---------------- fp16 helpers ----------------
__device__ __forceinline__ float4 load_half4(const __half* p) {
    uint2 u = *(const uint2*)p;
    __half2 a = *(__half2*)&u.x;
    __half2 b = *(__half2*)&u.y;
    float2 fa = __half22float2(a), fb = __half22float2(b);
    return make_float4(fa.x, fa.y, fb.x, fb.y);
}
__device__ __forceinline__ unsigned int smem_u32(const void* p) {
    return (unsigned int)__cvta_generic_to_shared(p);
}

// ---------------- zero kernels (split across streams) ----------------
__global__ void zero_scores_kernel() {
    int i = blockIdx.x * blockDim.x + threadIdx.x;
    if (i < Nn) { g_ssrc2[i] = 0.f; g_sdst2[i] = 0.f; }
    if (i < Nn * NH) { g_ssrc1[i] = 0.f; g_sdst1[i] = 0.f; }
}
__global__ void zero_counts_kernel() {
    int i = blockIdx.x * blockDim.x + threadIdx.x;
    if (i < Nn) { g_counts[i] = 0; g_fill[i] = 0; }
}

__global__ void count_kernel(const int* __restrict__ src) {
    int e = blockIdx.x * blockDim.x + threadIdx.x;
    if (e < Ee) atomicAdd(&g_counts[src[e]], 1);
}

__global__ void scan_block_kernel() {
    __shared__ int sh[1024];
    int i = blockIdx.x * 1024 + threadIdx.x;
    int v = (i < Nn) ? g_counts[i] : 0;
    sh[threadIdx.x] = v;
    __syncthreads();
    #pragma unroll
    for (int off = 1; off < 1024; off <<= 1) {
        int t = (threadIdx.x >= off) ? sh[threadIdx.x - off] : 0;
        __syncthreads();
        sh[threadIdx.x] += t;
        __syncthreads();
    }
    if (i < Nn) g_rowptr[i] = sh[threadIdx.x] - v;   // exclusive within block
    if (threadIdx.x == 1023) g_blksums[blockIdx.x] = sh[1023];
}

__global__ void scan_top_kernel() {
    __shared__ int sh[128];
    int i = threadIdx.x;
    int v = (i < NB_SCAN) ? g_blksums[i] : 0;
    sh[i] = v;
    __syncthreads();
    #pragma unroll
    for (int off = 1; off < 128; off <<= 1) {
        int t = (i >= off) ? sh[i - off] : 0;
        __syncthreads();
        sh[i] += t;
        __syncthreads();
    }
    if (i < NB_SCAN) g_blksums[i] = sh[i] - v;   // exclusive
}

__global__ void scan_add_kernel() {
    int i = blockIdx.x * blockDim.x + threadIdx.x;
    if (i < Nn) g_rowptr[i] += g_blksums[i >> 10];
    if (i == 0) g_rowptr[Nn] = Ee;
}

__global__ void scatter_kernel(const int* __restrict__ src, const int* __restrict__ dst) {
    int e = blockIdx.x * blockDim.x + threadIdx.x;
    if (e < Ee) {
        int s = src[e];
        int pos = g_rowptr[s] + atomicAdd(&g_fill[s], 1);
        g_dst[pos] = dst[e];
    }
}

// ---------------- conversions ----------------
__global__ void f2h_kernel(const float* __restrict__ in, __half* __restrict__ out, int nElem) {
    int i = (blockIdx.x * blockDim.x + threadIdx.x) * 4;
    if (i < nElem) {
        float4 v = *(const float4*)(in + i);
        __half2 a = __floats2half2_rn(v.x, v.y);
        __half2 b = __floats2half2_rn(v.z, v.w);
        uint2 u;
        u.x = *(unsigned int*)&a;
        u.y = *(unsigned int*)&b;
        *(uint2*)(out + i) = u;
    }
}

__global__ void prep_weights_kernel(const float* __restrict__ W0,
                                    const float* __restrict__ W_end,
                                    const float* __restrict__ W_heads) {
    int t = blockIdx.x * blockDim.x + threadIdx.x;
    if (t < INF * INF) g_W0h[t] = __float2half(W0[t]);
    if (t < F1 * OUTF) g_Wend_h[t] = __float2half(W_end[t]);
    if (t < INF * F1) {
        int i = t / F1;
        int c = t - i * F1;
        int h = c >> 6;
        int j = c & 63;
        g_Wcat_h[t] = __float2half(W_heads[(h * INF + i) * HIDF + j]);
    }
}

// ---------------- tensor-core GEMM: C[n,M] = A[n,K] @ B[K,M] ----------------
// fp16 A/B, fp32 accumulate. BM=128, BN=64, BK=32, 256 threads (8 warps, 4x2).
// SCORES: fused s_src/s_dst epilogue. STREAM_A: evict-first A loads.
template<bool HALF_OUT, bool BIAS, bool SCORES, bool STREAM_A>
__global__ void mma_gemm_kernel(const __half* __restrict__ A, const __half* __restrict__ B,
                                const float* __restrict__ bias, void* __restrict__ Cv,
                                const float* __restrict__ avec_base,
                                float* __restrict__ ssrc_arr, float* __restrict__ sdst_arr,
                                int sstride, int n, int K, int M) {
    __shared__ __half As[128][40];   // row stride 80 B (pad 8) -> conflict-free ldmatrix
    __shared__ __half Bs[32][72];    // row stride 144 B (pad 8)
    int t = threadIdx.x;
    int lane = t & 31, wid = t >> 5;
    int warp_m = wid & 3;            // 0..3 -> 32-row slab
    int warp_n = wid >> 2;           // 0..1 -> 32-col slab
    int bm = blockIdx.y * 128;
    int bn = blockIdx.x * 64;

    int ar = t >> 2;                 // 0..63 (A rows; +64 for second half)
    int ac = (t & 3) * 8;            // 0/8/16/24 (halves)
    int brow = t >> 3;               // 0..31
    int bcol = (t & 7) * 8;          // 0..56

    float c[2][4][4];
    #pragma unroll
    for (int mi = 0; mi < 2; mi++)
        #pragma unroll
        for (int ni = 0; ni < 4; ni++)
            #pragma unroll
            for (int q = 0; q < 4; q++) c[mi][ni][q] = 0.f;

    int r0 = bm + ar, r1 = bm + ar + 64;
    const __half* Ap0 = A + (size_t)r0 * K + ac;
    const __half* Ap1 = A + (size_t)r1 * K + ac;
    const __half* Bp  = B + (size_t)brow * M + bn + bcol;
    bool ok0 = r0 < n, ok1 = r1 < n;

    uint4 av0 = make_uint4(0u,0u,0u,0u), av1 = make_uint4(0u,0u,0u,0u);
    if (ok0) av0 = STREAM_A ? __ldcs((const uint4*)Ap0) : *(const uint4*)Ap0;
    if (ok1) av1 = STREAM_A ? __ldcs((const uint4*)Ap1) : *(const uint4*)Ap1;
    uint4 bv = *(const uint4*)Bp;

    for (int k0 = 0; k0 < K; k0 += 32) {
        __syncthreads();
        *(uint4*)&As[ar][ac]      = av0;
        *(uint4*)&As[ar + 64][ac] = av1;
        *(uint4*)&Bs[brow][bcol]  = bv;
        __syncthreads();

        int kn = k0 + 32;
        if (kn < K) {
            av0 = make_uint4(0u,0u,0u,0u); av1 = make_uint4(0u,0u,0u,0u);
            if (ok0) av0 = STREAM_A ? __ldcs((const uint4*)(Ap0 + kn)) : *(const uint4*)(Ap0 + kn);
            if (ok1) av1 = STREAM_A ? __ldcs((const uint4*)(Ap1 + kn)) : *(const uint4*)(Ap1 + kn);
            bv = *(const uint4*)(Bp + (size_t)kn * M);
        }

        #pragma unroll
        for (int ks = 0; ks < 32; ks += 16) {
            unsigned int afr[2][4], bfr[2][4];
            #pragma unroll
            for (int mi = 0; mi < 2; mi++) {
                unsigned int addr = smem_u32(&As[warp_m * 32 + mi * 16 + (lane & 15)][ks + (lane >> 4) * 8]);
                asm volatile("ldmatrix.sync.aligned.m8n8.x4.shared.b16 {%0,%1,%2,%3}, [%4];"
                    : "=r"(afr[mi][0]), "=r"(afr[mi][1]), "=r"(afr[mi][2]), "=r"(afr[mi][3])
                    : "r"(addr));
            }
            #pragma unroll
            for (int nb = 0; nb < 2; nb++) {
                unsigned int addr = smem_u32(&Bs[ks + (lane & 15)][warp_n * 32 + nb * 16 + (lane >> 4) * 8]);
                asm volatile("ldmatrix.sync.aligned.m8n8.x4.trans.shared.b16 {%0,%1,%2,%3}, [%4];"
                    : "=r"(bfr[nb][0]), "=r"(bfr[nb][1]), "=r"(bfr[nb][2]), "=r"(bfr[nb][3])
                    : "r"(addr));
            }
            #pragma unroll
            for (int mi = 0; mi < 2; mi++)
                #pragma unroll
                for (int ni = 0; ni < 4; ni++) {
                    unsigned int b0 = bfr[ni >> 1][(ni & 1) * 2 + 0];
                    unsigned int b1 = bfr[ni >> 1][(ni & 1) * 2 + 1];
                    asm volatile(
                        "mma.sync.aligned.m16n8k16.row.col.f32.f16.f16.f32 "
                        "{%0,%1,%2,%3}, {%4,%5,%6,%7}, {%8,%9}, {%0,%1,%2,%3};"
                        : "+f"(c[mi][ni][0]), "+f"(c[mi][ni][1]),
                          "+f"(c[mi][ni][2]), "+f"(c[mi][ni][3])
                        : "r"(afr[mi][0]), "r"(afr[mi][1]), "r"(afr[mi][2]), "r"(afr[mi][3]),
                          "r"(b0), "r"(b1));
                }
        }
    }

    int rb = bm + warp_m * 32;
    int cbw = bn + warp_n * 32;

    float a_s[4][2], a_d[4][2];
    if (SCORES) {
        const float* avec = avec_base + blockIdx.x * 128;
        #pragma unroll
        for (int ni = 0; ni < 4; ni++) {
            int colh = warp_n * 32 + ni * 8 + (lane & 3) * 2;
            float2 vs = *(const float2*)(avec + colh);
            float2 vd = *(const float2*)(avec + 64 + colh);
            a_s[ni][0] = vs.x; a_s[ni][1] = vs.y;
            a_d[ni][0] = vd.x; a_d[ni][1] = vd.y;
        }
    }

    #pragma unroll
    for (int mi = 0; mi < 2; mi++) {
        int rA = rb + mi * 16 + (lane >> 2);
        int rB = rA + 8;
        float psA = 0.f, pdA = 0.f, psB = 0.f, pdB = 0.f;
        #pragma unroll
        for (int ni = 0; ni < 4; ni++) {
            int cc = cbw + ni * 8 + (lane & 3) * 2;
            float b0 = 0.f, b1 = 0.f;
            if (BIAS) { b0 = bias[cc]; b1 = bias[cc + 1]; }
            if (HALF_OUT) {
                __half* C = (__half*)Cv;
                if (rA < n) *(__half2*)(C + (size_t)rA * M + cc) =
                    __floats2half2_rn(c[mi][ni][0] + b0, c[mi][ni][1] + b1);
                if (rB < n) *(__half2*)(C + (size_t)rB * M + cc) =
                    __floats2half2_rn(c[mi][ni][2] + b0, c[mi][ni][3] + b1);
            } else {
                float* C = (float*)Cv;
                if (rA < n) *(float2*)(C + (size_t)rA * M + cc) =
                    make_float2(c[mi][ni][0] + b0, c[mi][ni][1] + b1);
                if (rB < n) *(float2*)(C + (size_t)rB * M + cc) =
                    make_float2(c[mi][ni][2] + b0, c[mi][ni][3] + b1);
            }
            if (SCORES) {
                psA += c[mi][ni][0] * a_s[ni][0] + c[mi][ni][1] * a_s[ni][1];
                pdA += c[mi][ni][0] * a_d[ni][0] + c[mi][ni][1] * a_d[ni][1];
                psB += c[mi][ni][2] * a_s[ni][0] + c[mi][ni][3] * a_s[ni][1];
                pdB += c[mi][ni][2] * a_d[ni][0] + c[mi][ni][3] * a_d[ni][1];
            }
        }
        if (SCORES) {
            #pragma unroll
            for (int off = 1; off <= 2; off <<= 1) {
                psA += __shfl_xor_sync(0xffffffffu, psA, off);
                pdA += __shfl_xor_sync(0xffffffffu, pdA, off);
                psB += __shfl_xor_sync(0xffffffffu, psB, off);
                pdB += __shfl_xor_sync(0xffffffffu, pdB, off);
            }
            if ((lane & 3) == 0) {
                int h = blockIdx.x;
                if (rA < n) {
                    atomicAdd(&ssrc_arr[rA * sstride + h], psA);
                    atomicAdd(&sdst_arr[rA * sstride + h], pdA);
                }
                if (rB < n) {
                    atomicAdd(&ssrc_arr[rB * sstride + h], psB);
                    atomicAdd(&sdst_arr[rB * sstride + h], pdB);
                }
            }
        }
    }
}

// ---------------- layer-1 aggregation: 2 warps per node ----------------
// Each warp walks half the node's edge list with the same register footprint
// as the proven warp-per-node version; partials combined via smem.
// NOTE: rs[k] is HALF-warp-uniform (head 2k+hsel), so rowsum partials are
// published per (node, hsel, k) — lane 0 covers hsel=0, lane 16 hsel=1.
__global__ void agg1_kernel() {
    __shared__ float sacc[4][512];    // partial feature sums (node-in-block)
    __shared__ float srs[4][2][4];    // partial rowsums per (node, hsel, k)

    int gw   = (blockIdx.x * blockDim.x + threadIdx.x) >> 5;  // global warp
    int node = gw >> 1;
    int sub  = gw & 1;
    int nb   = (threadIdx.x >> 6);   // node-in-block 0..3
    int lane = threadIdx.x & 31;
    int hl   = lane & 7;
    int hsel = lane >> 4;

    bool active = node < Nn;
    float4 acc[4];
    float  rs[4];
    #pragma unroll
    for (int k = 0; k < 4; k++) { acc[k] = make_float4(0.f,0.f,0.f,0.f); rs[k] = 0.f; }

    if (active) {
        float ssrc = g_ssrc1[node * NH + hl];
        int beg = g_rowptr[node], end = g_rowptr[node + 1];
        int mid = beg + ((end - beg + 1) >> 1);
        int jb = sub ? mid : beg;
        int je = sub ? end : mid;

        for (int j = jb; j < je; j++) {
            int d = g_dst[j];
            float sc = ssrc + g_sdst1[d * NH + hl];
            float lr = sc > 0.f ? sc : ALPHA * sc;
            float w8 = __expf(-lr);
            const __half* hp = g_h1 + (size_t)d * F1;
            #pragma unroll
            for (int k = 0; k < 4; k++) {
                float w = __shfl_sync(0xffffffffu, w8, 2 * k + hsel);
                float4 v = load_half4(hp + k * 128 + lane * 4);
                acc[k].x += w * v.x; acc[k].y += w * v.y;
                acc[k].z += w * v.z; acc[k].w += w * v.w;
                rs[k] += w;
            }
        }
    }

    // combine: sub==1 publishes partials, sub==0 reduces and finalizes
    if (sub == 1) {
        #pragma unroll
        for (int k = 0; k < 4; k++)
            *(float4*)&sacc[nb][k * 128 + lane * 4] = acc[k];
        if ((lane & 15) == 0) {           // lane 0 -> hsel 0, lane 16 -> hsel 1
            #pragma unroll
            for (int k = 0; k < 4; k++) srs[nb][hsel][k] = rs[k];
        }
    }
    __syncthreads();
    if (sub == 0 && active) {
        __half* outp = g_out1 + (size_t)node * F1;
        #pragma unroll
        for (int k = 0; k < 4; k++) {
            float4 p = *(const float4*)&sacc[nb][k * 128 + lane * 4];
            acc[k].x += p.x; acc[k].y += p.y; acc[k].z += p.z; acc[k].w += p.w;
            float rtot = rs[k] + srs[nb][hsel][k];
            float inv = 1.f / (rtot + 1e-16f);
            float4 o;
            o.x = acc[k].x * inv; o.y = acc[k].y * inv;
            o.z = acc[k].z * inv; o.w = acc[k].w * inv;
            // ELU
            o.x = o.x > 0.f ? o.x : expm1f(o.x);
            o.y = o.y > 0.f ? o.y : expm1f(o.y);
            o.z = o.z > 0.f ? o.z : expm1f(o.z);
            o.w = o.w > 0.f ? o.w : expm1f(o.w);
            __half2 ha = __floats2half2_rn(o.x, o.y);
            __half2 hb = __floats2half2_rn(o.z, o.w);
            uint2 u;
            u.x = *(unsigned int*)&ha;
            u.y = *(unsigned int*)&hb;
            __stcs((uint2*)(outp + k * 128 + lane * 4), u);
        }
    }
}

// ---------------- layer-2 aggregation + softmax: warp per node (fp16 h2) ----------------
__global__ void agg2_kernel(float* __restrict__ out) {
    int node = (blockIdx.x * blockDim.x + threadIdx.x) >> 5;
    if (node >= Nn) return;
    int lane = threadIdx.x & 31;

    float ss = g_ssrc2[node];
    int beg = g_rowptr[node], end = g_rowptr[node + 1];
    float a0 = 0.f, a1 = 0.f, rs = 0.f;
    for (int j = beg; j < end; j++) {
        int d = g_dst[j];
        float sc = ss + g_sdst2[d];
        float lr = sc > 0.f ? sc : ALPHA * sc;
        float w = __expf(-lr);
        const __half2* hp = (const __half2*)(g_h2h + (size_t)d * OUTF);
        float2 f = __half22float2(hp[lane]);
        a0 += w * f.x;
        a1 += w * f.y;
        rs += w;
    }
    float inv = 1.f / (rs + 1e-16f);
    float v0 = a0 * inv, v1 = a1 * inv;

    float m = fmaxf(v0, v1);
    #pragma unroll
    for (int off = 16; off; off >>= 1) m = fmaxf(m, __shfl_xor_sync(0xffffffffu, m, off));
    float e0 = __expf(v0 - m), e1 = __expf(v1 - m);
    float s = e0 + e1;
    #pragma unroll
    for (int off = 16; off; off >>= 1) s += __shfl_xor_sync(0xffffffffu, s, off);
    float invs = 1.f / s;
    *(float2*)(out + (size_t)node * OUTF + lane * 2) = make_float2(e0 * invs, e1 * invs);
}

// ---------------- launch ----------------
extern "C" void kernel_launch(void* const* d_in, const int* in_sizes, int n_in,
                              void* d_out, int out_size) {
    const float* x       = (const float*)d_in[0];
    const int*   edges   = (const int*)  d_in[1];
    const float* W0      = (const float*)d_in[2];
    const float* b0      = (const float*)d_in[3];
    const float* W_heads = (const float*)d_in[4];
    const float* a_heads = (const float*)d_in[5];
    const float* W_end   = (const float*)d_in[6];
    const float* a_end   = (const float*)d_in[7];
    float* out = (float*)d_out;
    const int* src = edges;
    const int* dst = edges + Ee;

    __half *p_xh, *p_xph, *p_h1, *p_out1, *p_h2h, *p_W0h, *p_Wcath, *p_Wendh;
    float  *p_ssrc1, *p_sdst1, *p_ssrc2, *p_sdst2;
    cudaGetSymbolAddress((void**)&p_xh,    g_x_h);
    cudaGetSymbolAddress((void**)&p_xph,   g_xp_h);
    cudaGetSymbolAddress((void**)&p_h1,    g_h1);
    cudaGetSymbolAddress((void**)&p_out1,  g_out1);
    cudaGetSymbolAddress((void**)&p_h2h,   g_h2h);
    cudaGetSymbolAddress((void**)&p_W0h,   g_W0h);
    cudaGetSymbolAddress((void**)&p_Wcath, g_Wcat_h);
    cudaGetSymbolAddress((void**)&p_Wendh, g_Wend_h);
    cudaGetSymbolAddress((void**)&p_ssrc1, g_ssrc1);
    cudaGetSymbolAddress((void**)&p_sdst1, g_sdst1);
    cudaGetSymbolAddress((void**)&p_ssrc2, g_ssrc2);
    cudaGetSymbolAddress((void**)&p_sdst2, g_sdst2);

    // Side stream + fork/join events (host-side objects only; created once).
    static cudaStream_t s_csr = nullptr;
    static cudaEvent_t  ev_fork = nullptr, ev_join = nullptr;
    if (s_csr == nullptr) {
        cudaStreamCreateWithFlags(&s_csr, cudaStreamNonBlocking);
        cudaEventCreateWithFlags(&ev_fork, cudaEventDisableTiming);
        cudaEventCreateWithFlags(&ev_join, cudaEventDisableTiming);
    }

    // ---- fork: CSR chain on side stream ----
    cudaEventRecord(ev_fork, 0);
    cudaStreamWaitEvent(s_csr, ev_fork, 0);
    zero_counts_kernel<<<(Nn + 255) / 256, 256, 0, s_csr>>>();
    count_kernel<<<(Ee + 255) / 256, 256, 0, s_csr>>>(src);
    scan_block_kernel<<<NB_SCAN, 1024, 0, s_csr>>>();
    scan_top_kernel<<<1, 128, 0, s_csr>>>();
    scan_add_kernel<<<(Nn + 255) / 256, 256, 0, s_csr>>>();
    scatter_kernel<<<(Ee + 255) / 256, 256, 0, s_csr>>>(src, dst);
    cudaEventRecord(ev_join, s_csr);

    // ---- main stream: dense chain (independent of CSR until agg1) ----
    zero_scores_kernel<<<(Nn * NH + 255) / 256, 256>>>();
    f2h_kernel<<<(Nn * INF / 4 + 255) / 256, 256>>>(x, p_xh, Nn * INF);
    prep_weights_kernel<<<(INF * F1 + 255) / 256, 256>>>(W0, W_end, W_heads);

    const int GY = (Nn + 127) / 128;   // 782

    // xp = x @ W0 + b0   (fp16 out)
    mma_gemm_kernel<true, true, false, false><<<dim3(INF / 64, GY), 256>>>(
        p_xh, p_W0h, b0, p_xph, nullptr, nullptr, nullptr, 0, Nn, INF, INF);
    // h1 = xp @ Wcat     (fp16 out, all 8 heads) + fused s1 scores
    mma_gemm_kernel<true, false, true, false><<<dim3(F1 / 64, GY), 256>>>(
        p_xph, p_Wcath, nullptr, p_h1, a_heads, p_ssrc1, p_sdst1, NH, Nn, INF, F1);

    // ---- join: agg1 needs both the CSR and the dense chain ----
    cudaStreamWaitEvent(0, ev_join, 0);

    // layer-1 aggregation + ELU -> out1 [N,512] (fp16); 2 warps/node
    agg1_kernel<<<(Nn * 64 + 255) / 256, 256>>>();
    // h2 = out1 @ W_end  (fp16 out; A read-once -> streaming) + fused s2 scores
    mma_gemm_kernel<true, false, true, true><<<dim3(OUTF / 64, GY), 256>>>(
        p_out1, p_Wendh, nullptr, p_h2h, a_end, p_ssrc2, p_sdst2, 1, Nn, F1, OUTF);
    // layer-2 aggregation + softmax -> output
    agg2_kernel<<<(Nn + 7) / 8, 256>>>(out);
}

// round 15
// speedup vs baseline: 1.1129x; 1.1129x over previous
#include <cuda_runtime.h>
#include <cuda_fp16.h>
#include <math.h>
#include <stdint.h>

// Problem constants (fixed by the reference)
#define Nn   100000
#define Ee   1600000
#define INF  128
#define HIDF 64
#define NH   8
#define F1   512      // NH*HIDF
#define OUTF 64
#define ALPHA 0.2f
#define NB_SCAN ((Nn + 1023) / 1024)   // 98

// ---------------- device scratch (no allocations allowed) ----------------
__device__ __half g_x_h[(size_t)Nn * INF];        // 25.6 MB
__device__ __half g_xp_h[(size_t)Nn * INF];       // 25.6 MB
__device__ __half g_h1[(size_t)Nn * F1];          // 102.4 MB (~fits L2)
__device__ __half g_out1[(size_t)Nn * F1];        // 102.4 MB
__device__ __half g_h2h[Nn * OUTF];               // 12.8 MB (L2-resident)
__device__ __half g_W0h[INF * INF];
__device__ __half g_Wcat_h[INF * F1];             // repacked head weights (fp16)
__device__ __half g_Wend_h[F1 * OUTF];
__device__ float  g_ssrc1[Nn * NH];
__device__ float  g_sdst1[Nn * NH];
__device__ float  g_ssrc2[Nn];
__device__ float  g_sdst2[Nn];
__device__ int    g_counts[Nn];
__device__ int    g_fill[Nn];
__device__ int    g_rowptr[Nn + 1];
__device__ int    g_dst[Ee];
__device__ int    g_blksums[128];

// ---------------- fp16 helpers ----------------
__device__ __forceinline__ float4 load_half4(const __half* p) {
    uint2 u = *(const uint2*)p;
    __half2 a = *(__half2*)&u.x;
    __half2 b = *(__half2*)&u.y;
    float2 fa = __half22float2(a), fb = __half22float2(b);
    return make_float4(fa.x, fa.y, fb.x, fb.y);
}
// L2-only load (skip L1 fill): for random gathers with no L1 reuse.
__device__ __forceinline__ float4 load_half4_cg(const __half* p) {
    uint2 u = __ldcg((const uint2*)p);
    __half2 a = *(__half2*)&u.x;
    __half2 b = *(__half2*)&u.y;
    float2 fa = __half22float2(a), fb = __half22float2(b);
    return make_float4(fa.x, fa.y, fb.x, fb.y);
}
__device__ __forceinline__ unsigned int smem_u32(const void* p) {
    return (unsigned int)__cvta_generic_to_shared(p);
}

// ---------------- CSR-stream zero ----------------
__global__ void zero_counts_kernel() {
    int i = blockIdx.x * blockDim.x + threadIdx.x;
    if (i < Nn) { g_counts[i] = 0; g_fill[i] = 0; }
}

__global__ void count_kernel(const int* __restrict__ src) {
    int e = blockIdx.x * blockDim.x + threadIdx.x;
    if (e < Ee) atomicAdd(&g_counts[src[e]], 1);
}

__global__ void scan_block_kernel() {
    __shared__ int sh[1024];
    int i = blockIdx.x * 1024 + threadIdx.x;
    int v = (i < Nn) ? g_counts[i] : 0;
    sh[threadIdx.x] = v;
    __syncthreads();
    #pragma unroll
    for (int off = 1; off < 1024; off <<= 1) {
        int t = (threadIdx.x >= off) ? sh[threadIdx.x - off] : 0;
        __syncthreads();
        sh[threadIdx.x] += t;
        __syncthreads();
    }
    if (i < Nn) g_rowptr[i] = sh[threadIdx.x] - v;   // exclusive within block
    if (threadIdx.x == 1023) g_blksums[blockIdx.x] = sh[1023];
}

__global__ void scan_top_kernel() {
    __shared__ int sh[128];
    int i = threadIdx.x;
    int v = (i < NB_SCAN) ? g_blksums[i] : 0;
    sh[i] = v;
    __syncthreads();
    #pragma unroll
    for (int off = 1; off < 128; off <<= 1) {
        int t = (i >= off) ? sh[i - off] : 0;
        __syncthreads();
        sh[i] += t;
        __syncthreads();
    }
    if (i < NB_SCAN) g_blksums[i] = sh[i] - v;   // exclusive
}

__global__ void scan_add_kernel() {
    int i = blockIdx.x * blockDim.x + threadIdx.x;
    if (i < Nn) g_rowptr[i] += g_blksums[i >> 10];
    if (i == 0) g_rowptr[Nn] = Ee;
}

__global__ void scatter_kernel(const int* __restrict__ src, const int* __restrict__ dst) {
    int e = blockIdx.x * blockDim.x + threadIdx.x;
    if (e < Ee) {
        int s = src[e];
        int pos = g_rowptr[s] + atomicAdd(&g_fill[s], 1);
        g_dst[pos] = dst[e];
    }
}

// ---------------- conversions ----------------
__global__ void f2h_kernel(const float* __restrict__ in, __half* __restrict__ out, int nElem) {
    int i = (blockIdx.x * blockDim.x + threadIdx.x) * 4;
    if (i < nElem) {
        float4 v = *(const float4*)(in + i);
        __half2 a = __floats2half2_rn(v.x, v.y);
        __half2 b = __floats2half2_rn(v.z, v.w);
        uint2 u;
        u.x = *(unsigned int*)&a;
        u.y = *(unsigned int*)&b;
        *(uint2*)(out + i) = u;
    }
}

// Weight conversions + score-accumulator zeroing in ONE kernel
// (grid covers Nn*NH = 800000 threads; weight work is a prefix subset).
__global__ void prep_kernel(const float* __restrict__ W0,
                            const float* __restrict__ W_end,
                            const float* __restrict__ W_heads) {
    int t = blockIdx.x * blockDim.x + threadIdx.x;
    if (t < INF * INF) g_W0h[t] = __float2half(W0[t]);
    if (t < F1 * OUTF) g_Wend_h[t] = __float2half(W_end[t]);
    if (t < INF * F1) {
        int i = t / F1;
        int c = t - i * F1;
        int h = c >> 6;
        int j = c & 63;
        g_Wcat_h[t] = __float2half(W_heads[(h * INF + i) * HIDF + j]);
    }
    if (t < Nn) { g_ssrc2[t] = 0.f; g_sdst2[t] = 0.f; }
    if (t < Nn * NH) { g_ssrc1[t] = 0.f; g_sdst1[t] = 0.f; }
}

// ---------------- tensor-core GEMM: C[n,M] = A[n,K] @ B[K,M] ----------------
// fp16 A/B, fp32 accumulate. BM=128, BN=64, BK=32, 256 threads (8 warps, 4x2).
// SCORES: fused s_src/s_dst epilogue. STREAM_A: evict-first A loads.
template<bool HALF_OUT, bool BIAS, bool SCORES, bool STREAM_A>
__global__ void mma_gemm_kernel(const __half* __restrict__ A, const __half* __restrict__ B,
                                const float* __restrict__ bias, void* __restrict__ Cv,
                                const float* __restrict__ avec_base,
                                float* __restrict__ ssrc_arr, float* __restrict__ sdst_arr,
                                int sstride, int n, int K, int M) {
    __shared__ __half As[128][40];   // row stride 80 B (pad 8) -> conflict-free ldmatrix
    __shared__ __half Bs[32][72];    // row stride 144 B (pad 8)
    int t = threadIdx.x;
    int lane = t & 31, wid = t >> 5;
    int warp_m = wid & 3;            // 0..3 -> 32-row slab
    int warp_n = wid >> 2;           // 0..1 -> 32-col slab
    int bm = blockIdx.y * 128;
    int bn = blockIdx.x * 64;

    int ar = t >> 2;                 // 0..63 (A rows; +64 for second half)
    int ac = (t & 3) * 8;            // 0/8/16/24 (halves)
    int brow = t >> 3;               // 0..31
    int bcol = (t & 7) * 8;          // 0..56

    float c[2][4][4];
    #pragma unroll
    for (int mi = 0; mi < 2; mi++)
        #pragma unroll
        for (int ni = 0; ni < 4; ni++)
            #pragma unroll
            for (int q = 0; q < 4; q++) c[mi][ni][q] = 0.f;

    int r0 = bm + ar, r1 = bm + ar + 64;
    const __half* Ap0 = A + (size_t)r0 * K + ac;
    const __half* Ap1 = A + (size_t)r1 * K + ac;
    const __half* Bp  = B + (size_t)brow * M + bn + bcol;
    bool ok0 = r0 < n, ok1 = r1 < n;

    uint4 av0 = make_uint4(0u,0u,0u,0u), av1 = make_uint4(0u,0u,0u,0u);
    if (ok0) av0 = STREAM_A ? __ldcs((const uint4*)Ap0) : *(const uint4*)Ap0;
    if (ok1) av1 = STREAM_A ? __ldcs((const uint4*)Ap1) : *(const uint4*)Ap1;
    uint4 bv = *(const uint4*)Bp;

    for (int k0 = 0; k0 < K; k0 += 32) {
        __syncthreads();
        *(uint4*)&As[ar][ac]      = av0;
        *(uint4*)&As[ar + 64][ac] = av1;
        *(uint4*)&Bs[brow][bcol]  = bv;
        __syncthreads();

        int kn = k0 + 32;
        if (kn < K) {
            av0 = make_uint4(0u,0u,0u,0u); av1 = make_uint4(0u,0u,0u,0u);
            if (ok0) av0 = STREAM_A ? __ldcs((const uint4*)(Ap0 + kn)) : *(const uint4*)(Ap0 + kn);
            if (ok1) av1 = STREAM_A ? __ldcs((const uint4*)(Ap1 + kn)) : *(const uint4*)(Ap1 + kn);
            bv = *(const uint4*)(Bp + (size_t)kn * M);
        }

        #pragma unroll
        for (int ks = 0; ks < 32; ks += 16) {
            unsigned int afr[2][4], bfr[2][4];
            #pragma unroll
            for (int mi = 0; mi < 2; mi++) {
                unsigned int addr = smem_u32(&As[warp_m * 32 + mi * 16 + (lane & 15)][ks + (lane >> 4) * 8]);
                asm volatile("ldmatrix.sync.aligned.m8n8.x4.shared.b16 {%0,%1,%2,%3}, [%4];"
                    : "=r"(afr[mi][0]), "=r"(afr[mi][1]), "=r"(afr[mi][2]), "=r"(afr[mi][3])
                    : "r"(addr));
            }
            #pragma unroll
            for (int nb = 0; nb < 2; nb++) {
                unsigned int addr = smem_u32(&Bs[ks + (lane & 15)][warp_n * 32 + nb * 16 + (lane >> 4) * 8]);
                asm volatile("ldmatrix.sync.aligned.m8n8.x4.trans.shared.b16 {%0,%1,%2,%3}, [%4];"
                    : "=r"(bfr[nb][0]), "=r"(bfr[nb][1]), "=r"(bfr[nb][2]), "=r"(bfr[nb][3])
                    : "r"(addr));
            }
            #pragma unroll
            for (int mi = 0; mi < 2; mi++)
                #pragma unroll
                for (int ni = 0; ni < 4; ni++) {
                    unsigned int b0 = bfr[ni >> 1][(ni & 1) * 2 + 0];
                    unsigned int b1 = bfr[ni >> 1][(ni & 1) * 2 + 1];
                    asm volatile(
                        "mma.sync.aligned.m16n8k16.row.col.f32.f16.f16.f32 "
                        "{%0,%1,%2,%3}, {%4,%5,%6,%7}, {%8,%9}, {%0,%1,%2,%3};"
                        : "+f"(c[mi][ni][0]), "+f"(c[mi][ni][1]),
                          "+f"(c[mi][ni][2]), "+f"(c[mi][ni][3])
                        : "r"(afr[mi][0]), "r"(afr[mi][1]), "r"(afr[mi][2]), "r"(afr[mi][3]),
                          "r"(b0), "r"(b1));
                }
        }
    }

    int rb = bm + warp_m * 32;
    int cbw = bn + warp_n * 32;

    float a_s[4][2], a_d[4][2];
    if (SCORES) {
        const float* avec = avec_base + blockIdx.x * 128;
        #pragma unroll
        for (int ni = 0; ni < 4; ni++) {
            int colh = warp_n * 32 + ni * 8 + (lane & 3) * 2;
            float2 vs = *(const float2*)(avec + colh);
            float2 vd = *(const float2*)(avec + 64 + colh);
            a_s[ni][0] = vs.x; a_s[ni][1] = vs.y;
            a_d[ni][0] = vd.x; a_d[ni][1] = vd.y;
        }
    }

    #pragma unroll
    for (int mi = 0; mi < 2; mi++) {
        int rA = rb + mi * 16 + (lane >> 2);
        int rB = rA + 8;
        float psA = 0.f, pdA = 0.f, psB = 0.f, pdB = 0.f;
        #pragma unroll
        for (int ni = 0; ni < 4; ni++) {
            int cc = cbw + ni * 8 + (lane & 3) * 2;
            float b0 = 0.f, b1 = 0.f;
            if (BIAS) { b0 = bias[cc]; b1 = bias[cc + 1]; }
            if (HALF_OUT) {
                __half* C = (__half*)Cv;
                if (rA < n) *(__half2*)(C + (size_t)rA * M + cc) =
                    __floats2half2_rn(c[mi][ni][0] + b0, c[mi][ni][1] + b1);
                if (rB < n) *(__half2*)(C + (size_t)rB * M + cc) =
                    __floats2half2_rn(c[mi][ni][2] + b0, c[mi][ni][3] + b1);
            } else {
                float* C = (float*)Cv;
                if (rA < n) *(float2*)(C + (size_t)rA * M + cc) =
                    make_float2(c[mi][ni][0] + b0, c[mi][ni][1] + b1);
                if (rB < n) *(float2*)(C + (size_t)rB * M + cc) =
                    make_float2(c[mi][ni][2] + b0, c[mi][ni][3] + b1);
            }
            if (SCORES) {
                psA += c[mi][ni][0] * a_s[ni][0] + c[mi][ni][1] * a_s[ni][1];
                pdA += c[mi][ni][0] * a_d[ni][0] + c[mi][ni][1] * a_d[ni][1];
                psB += c[mi][ni][2] * a_s[ni][0] + c[mi][ni][3] * a_s[ni][1];
                pdB += c[mi][ni][2] * a_d[ni][0] + c[mi][ni][3] * a_d[ni][1];
            }
        }
        if (SCORES) {
            #pragma unroll
            for (int off = 1; off <= 2; off <<= 1) {
                psA += __shfl_xor_sync(0xffffffffu, psA, off);
                pdA += __shfl_xor_sync(0xffffffffu, pdA, off);
                psB += __shfl_xor_sync(0xffffffffu, psB, off);
                pdB += __shfl_xor_sync(0xffffffffu, pdB, off);
            }
            if ((lane & 3) == 0) {
                int h = blockIdx.x;
                if (rA < n) {
                    atomicAdd(&ssrc_arr[rA * sstride + h], psA);
                    atomicAdd(&sdst_arr[rA * sstride + h], pdA);
                }
                if (rB < n) {
                    atomicAdd(&ssrc_arr[rB * sstride + h], psB);
                    atomicAdd(&sdst_arr[rB * sstride + h], pdB);
                }
            }
        }
    }
}

// ---------------- layer-1 aggregation: warp per node (fp16 gather, fp32 accum) ----------------
__global__ void agg1_kernel() {
    int node = (blockIdx.x * blockDim.x + threadIdx.x) >> 5;
    if (node >= Nn) return;
    int lane = threadIdx.x & 31;
    int hl   = lane & 7;        // head whose weight this lane computes
    int hsel = lane >> 4;       // 0/1: which head within each 128-col chunk

    float ssrc = g_ssrc1[node * NH + hl];
    int beg = g_rowptr[node], end = g_rowptr[node + 1];

    float4 acc[4];
    float  rs[4];
    #pragma unroll
    for (int k = 0; k < 4; k++) { acc[k] = make_float4(0.f,0.f,0.f,0.f); rs[k] = 0.f; }

    for (int j = beg; j < end; j++) {
        int d = g_dst[j];
        float sc = ssrc + g_sdst1[d * NH + hl];
        float lr = sc > 0.f ? sc : ALPHA * sc;
        float w8 = __expf(-lr);
        const __half* hp = g_h1 + (size_t)d * F1;
        #pragma unroll
        for (int k = 0; k < 4; k++) {
            float w = __shfl_sync(0xffffffffu, w8, 2 * k + hsel);
            float4 v = load_half4_cg(hp + k * 128 + lane * 4);   // L2-only: no L1 reuse
            acc[k].x += w * v.x; acc[k].y += w * v.y;
            acc[k].z += w * v.z; acc[k].w += w * v.w;
            rs[k] += w;
        }
    }

    __half* outp = g_out1 + (size_t)node * F1;
    #pragma unroll
    for (int k = 0; k < 4; k++) {
        float inv = 1.f / (rs[k] + 1e-16f);
        float4 o;
        o.x = acc[k].x * inv; o.y = acc[k].y * inv;
        o.z = acc[k].z * inv; o.w = acc[k].w * inv;
        // ELU
        o.x = o.x > 0.f ? o.x : expm1f(o.x);
        o.y = o.y > 0.f ? o.y : expm1f(o.y);
        o.z = o.z > 0.f ? o.z : expm1f(o.z);
        o.w = o.w > 0.f ? o.w : expm1f(o.w);
        // evict-first store: out1 is write-once here, read-once by GEMM3.
        __half2 ha = __floats2half2_rn(o.x, o.y);
        __half2 hb = __floats2half2_rn(o.z, o.w);
        uint2 u;
        u.x = *(unsigned int*)&ha;
        u.y = *(unsigned int*)&hb;
        __stcs((uint2*)(outp + k * 128 + lane * 4), u);
    }
}

// ---------------- layer-2 aggregation + softmax: warp per node (fp16 h2) ----------------
__global__ void agg2_kernel(float* __restrict__ out) {
    int node = (blockIdx.x * blockDim.x + threadIdx.x) >> 5;
    if (node >= Nn) return;
    int lane = threadIdx.x & 31;

    float ss = g_ssrc2[node];
    int beg = g_rowptr[node], end = g_rowptr[node + 1];
    float a0 = 0.f, a1 = 0.f, rs = 0.f;
    for (int j = beg; j < end; j++) {
        int d = g_dst[j];
        float sc = ss + g_sdst2[d];
        float lr = sc > 0.f ? sc : ALPHA * sc;
        float w = __expf(-lr);
        const __half2* hp = (const __half2*)(g_h2h + (size_t)d * OUTF);
        unsigned int uu = __ldcg((const unsigned int*)(hp + lane));  // L2-only gather
        float2 f = __half22float2(*(__half2*)&uu);
        a0 += w * f.x;
        a1 += w * f.y;
        rs += w;
    }
    float inv = 1.f / (rs + 1e-16f);
    float v0 = a0 * inv, v1 = a1 * inv;

    float m = fmaxf(v0, v1);
    #pragma unroll
    for (int off = 16; off; off >>= 1) m = fmaxf(m, __shfl_xor_sync(0xffffffffu, m, off));
    float e0 = __expf(v0 - m), e1 = __expf(v1 - m);
    float s = e0 + e1;
    #pragma unroll
    for (int off = 16; off; off >>= 1) s += __shfl_xor_sync(0xffffffffu, s, off);
    float invs = 1.f / s;
    *(float2*)(out + (size_t)node * OUTF + lane * 2) = make_float2(e0 * invs, e1 * invs);
}

// ---------------- launch ----------------
extern "C" void kernel_launch(void* const* d_in, const int* in_sizes, int n_in,
                              void* d_out, int out_size) {
    const float* x       = (const float*)d_in[0];
    const int*   edges   = (const int*)  d_in[1];
    const float* W0      = (const float*)d_in[2];
    const float* b0      = (const float*)d_in[3];
    const float* W_heads = (const float*)d_in[4];
    const float* a_heads = (const float*)d_in[5];
    const float* W_end   = (const float*)d_in[6];
    const float* a_end   = (const float*)d_in[7];
    float* out = (float*)d_out;
    const int* src = edges;
    const int* dst = edges + Ee;

    __half *p_xh, *p_xph, *p_h1, *p_out1, *p_h2h, *p_W0h, *p_Wcath, *p_Wendh;
    float  *p_ssrc1, *p_sdst1, *p_ssrc2, *p_sdst2;
    cudaGetSymbolAddress((void**)&p_xh,    g_x_h);
    cudaGetSymbolAddress((void**)&p_xph,   g_xp_h);
    cudaGetSymbolAddress((void**)&p_h1,    g_h1);
    cudaGetSymbolAddress((void**)&p_out1,  g_out1);
    cudaGetSymbolAddress((void**)&p_h2h,   g_h2h);
    cudaGetSymbolAddress((void**)&p_W0h,   g_W0h);
    cudaGetSymbolAddress((void**)&p_Wcath, g_Wcat_h);
    cudaGetSymbolAddress((void**)&p_Wendh, g_Wend_h);
    cudaGetSymbolAddress((void**)&p_ssrc1, g_ssrc1);
    cudaGetSymbolAddress((void**)&p_sdst1, g_sdst1);
    cudaGetSymbolAddress((void**)&p_ssrc2, g_ssrc2);
    cudaGetSymbolAddress((void**)&p_sdst2, g_sdst2);

    // Side stream + fork/join events (host-side objects only; created once).
    static cudaStream_t s_csr = nullptr;
    static cudaEvent_t  ev_fork = nullptr, ev_join = nullptr;
    if (s_csr == nullptr) {
        cudaStreamCreateWithFlags(&s_csr, cudaStreamNonBlocking);
        cudaEventCreateWithFlags(&ev_fork, cudaEventDisableTiming);
        cudaEventCreateWithFlags(&ev_join, cudaEventDisableTiming);
    }

    // ---- fork: CSR chain on side stream ----
    cudaEventRecord(ev_fork, 0);
    cudaStreamWaitEvent(s_csr, ev_fork, 0);
    zero_counts_kernel<<<(Nn + 255) / 256, 256, 0, s_csr>>>();
    count_kernel<<<(Ee + 255) / 256, 256, 0, s_csr>>>(src);
    scan_block_kernel<<<NB_SCAN, 1024, 0, s_csr>>>();
    scan_top_kernel<<<1, 128, 0, s_csr>>>();
    scan_add_kernel<<<(Nn + 255) / 256, 256, 0, s_csr>>>();
    scatter_kernel<<<(Ee + 255) / 256, 256, 0, s_csr>>>(src, dst);
    cudaEventRecord(ev_join, s_csr);

    // ---- main stream: dense chain (independent of CSR until agg1) ----
    f2h_kernel<<<(Nn * INF / 4 + 255) / 256, 256>>>(x, p_xh, Nn * INF);
    prep_kernel<<<(Nn * NH + 255) / 256, 256>>>(W0, W_end, W_heads);

    const int GY = (Nn + 127) / 128;   // 782

    // xp = x @ W0 + b0   (fp16 out)
    mma_gemm_kernel<true, true, false, false><<<dim3(INF / 64, GY), 256>>>(
        p_xh, p_W0h, b0, p_xph, nullptr, nullptr, nullptr, 0, Nn, INF, INF);
    // h1 = xp @ Wcat     (fp16 out, all 8 heads) + fused s1 scores
    mma_gemm_kernel<true, false, true, false><<<dim3(F1 / 64, GY), 256>>>(
        p_xph, p_Wcath, nullptr, p_h1, a_heads, p_ssrc1, p_sdst1, NH, Nn, INF, F1);

    // ---- join: agg1 needs both the CSR and the dense chain ----
    cudaStreamWaitEvent(0, ev_join, 0);

    // layer-1 aggregation + ELU -> out1 [N,512] (fp16)
    agg1_kernel<<<(Nn + 7) / 8, 256>>>();
    // h2 = out1 @ W_end  (fp16 out; A read-once -> streaming) + fused s2 scores
    mma_gemm_kernel<true, false, true, true><<<dim3(OUTF / 64, GY), 256>>>(
        p_out1, p_Wendh, nullptr, p_h2h, a_end, p_ssrc2, p_sdst2, 1, Nn, F1, OUTF);
    // layer-2 aggregation + softmax -> output
    agg2_kernel<<<(Nn + 7) / 8, 256>>>(out);
}

// round 16
// speedup vs baseline: 1.1338x; 1.0188x over previous
#include <cuda_runtime.h>
#include <cuda_fp16.h>
#include <math.h>
#include <stdint.h>

// Problem constants (fixed by the reference)
#define Nn   100000
#define Ee   1600000
#define INF  128
#define HIDF 64
#define NH   8
#define F1   512      // NH*HIDF
#define OUTF 64
#define ALPHA 0.2f
#define NB_SCAN ((Nn + 1023) / 1024)   // 98

// ---------------- device scratch (no allocations allowed) ----------------
__device__ __half g_x_h[(size_t)Nn * INF];        // 25.6 MB
__device__ __half g_h1[(size_t)Nn * F1];          // 102.4 MB (~fits L2)
__device__ __half g_out1[(size_t)Nn * F1];        // 102.4 MB
__device__ __half g_h2h[Nn * OUTF];               // 12.8 MB (L2-resident)
__device__ __half g_W0h[INF * INF];
__device__ __half g_Wcat_h[INF * F1];             // repacked head weights (fp16)
__device__ __half g_Wend_h[F1 * OUTF];
__device__ float  g_ssrc1[Nn * NH];
__device__ float  g_sdst1[Nn * NH];
__device__ float  g_ssrc2[Nn];
__device__ float  g_sdst2[Nn];
__device__ int    g_counts[Nn];
__device__ int    g_fill[Nn];
__device__ int    g_rowptr[Nn + 1];
__device__ int    g_dst[Ee];
__device__ int    g_blksums[128];

// ---------------- fp16 helpers ----------------
// L2-only load (skip L1 fill): for random gathers with no L1 reuse.
__device__ __forceinline__ float4 load_half4_cg(const __half* p) {
    uint2 u = __ldcg((const uint2*)p);
    __half2 a = *(__half2*)&u.x;
    __half2 b = *(__half2*)&u.y;
    float2 fa = __half22float2(a), fb = __half22float2(b);
    return make_float4(fa.x, fa.y, fb.x, fb.y);
}
__device__ __forceinline__ unsigned int smem_u32(const void* p) {
    return (unsigned int)__cvta_generic_to_shared(p);
}

// ---------------- CSR-stream zero ----------------
__global__ void zero_counts_kernel() {
    int i = blockIdx.x * blockDim.x + threadIdx.x;
    if (i < Nn) { g_counts[i] = 0; g_fill[i] = 0; }
}

__global__ void count_kernel(const int* __restrict__ src) {
    int e = blockIdx.x * blockDim.x + threadIdx.x;
    if (e < Ee) atomicAdd(&g_counts[src[e]], 1);
}

__global__ void scan_block_kernel() {
    __shared__ int sh[1024];
    int i = blockIdx.x * 1024 + threadIdx.x;
    int v = (i < Nn) ? g_counts[i] : 0;
    sh[threadIdx.x] = v;
    __syncthreads();
    #pragma unroll
    for (int off = 1; off < 1024; off <<= 1) {
        int t = (threadIdx.x >= off) ? sh[threadIdx.x - off] : 0;
        __syncthreads();
        sh[threadIdx.x] += t;
        __syncthreads();
    }
    if (i < Nn) g_rowptr[i] = sh[threadIdx.x] - v;   // exclusive within block
    if (threadIdx.x == 1023) g_blksums[blockIdx.x] = sh[1023];
}

__global__ void scan_top_kernel() {
    __shared__ int sh[128];
    int i = threadIdx.x;
    int v = (i < NB_SCAN) ? g_blksums[i] : 0;
    sh[i] = v;
    __syncthreads();
    #pragma unroll
    for (int off = 1; off < 128; off <<= 1) {
        int t = (i >= off) ? sh[i - off] : 0;
        __syncthreads();
        sh[i] += t;
        __syncthreads();
    }
    if (i < NB_SCAN) g_blksums[i] = sh[i] - v;   // exclusive
}

__global__ void scan_add_kernel() {
    int i = blockIdx.x * blockDim.x + threadIdx.x;
    if (i < Nn) g_rowptr[i] += g_blksums[i >> 10];
    if (i == 0) g_rowptr[Nn] = Ee;
}

__global__ void scatter_kernel(const int* __restrict__ src, const int* __restrict__ dst) {
    int e = blockIdx.x * blockDim.x + threadIdx.x;
    if (e < Ee) {
        int s = src[e];
        int pos = g_rowptr[s] + atomicAdd(&g_fill[s], 1);
        g_dst[pos] = dst[e];
    }
}

// ---------------- conversions ----------------
__global__ void f2h_kernel(const float* __restrict__ in, __half* __restrict__ out, int nElem) {
    int i = (blockIdx.x * blockDim.x + threadIdx.x) * 4;
    if (i < nElem) {
        float4 v = *(const float4*)(in + i);
        __half2 a = __floats2half2_rn(v.x, v.y);
        __half2 b = __floats2half2_rn(v.z, v.w);
        uint2 u;
        u.x = *(unsigned int*)&a;
        u.y = *(unsigned int*)&b;
        *(uint2*)(out + i) = u;
    }
}

// Weight conversions + score-accumulator zeroing in ONE kernel.
__global__ void prep_kernel(const float* __restrict__ W0,
                            const float* __restrict__ W_end,
                            const float* __restrict__ W_heads) {
    int t = blockIdx.x * blockDim.x + threadIdx.x;
    if (t < INF * INF) g_W0h[t] = __float2half(W0[t]);
    if (t < F1 * OUTF) g_Wend_h[t] = __float2half(W_end[t]);
    if (t < INF * F1) {
        int i = t / F1;
        int c = t - i * F1;
        int h = c >> 6;
        int j = c & 63;
        g_Wcat_h[t] = __float2half(W_heads[(h * INF + i) * HIDF + j]);
    }
    if (t < Nn) { g_ssrc2[t] = 0.f; g_sdst2[t] = 0.f; }
    if (t < Nn * NH) { g_ssrc1[t] = 0.f; g_sdst1[t] = 0.f; }
}

// ---------------- FUSED GEMM1+GEMM2 ----------------
// Stage A: XP[128,128] = x_h @ W0 + b0  (fp32 acc, fp16 into smem)
// Stage B: per head h: h1[:,h*64..] = XP @ Wcat[:,h*64..] + fused s1 scores.
// All ldmatrix/fragment patterns identical to the proven mma_gemm_kernel.
__global__ void fused_g12_kernel(const __half* __restrict__ A,    // x_h [n,128]
                                 const __half* __restrict__ B0,   // W0h [128,128]
                                 const float* __restrict__ bias,  // b0
                                 const __half* __restrict__ Bc,   // Wcat_h [128,512]
                                 const float* __restrict__ a_heads,
                                 __half* __restrict__ C,          // h1 [n,512]
                                 float* __restrict__ ssrc_arr,
                                 float* __restrict__ sdst_arr,
                                 int n) {
    __shared__ __half XPs[128][136];  // 34816 B; row stride 272 B (68w % 32 = 4 -> conflict-free ldmatrix)
    __shared__ __half Bs[32][136];    // 8704 B; used 128-wide (stage A) / 64-wide (stage B)
    __half (*As)[40] = (__half (*)[40])XPs;   // alias: As dead before XPs is written

    int t = threadIdx.x;
    int lane = t & 31, wid = t >> 5;
    int warp_m = wid & 3;             // 32-row slab
    int warp_n = wid >> 2;            // 32-col slab (within each 64-col half/head)
    int bm = blockIdx.x * 128;

    // staging indices
    int ar = t >> 2, ac = (t & 3) * 8;       // A tile (proven pattern)
    int br1 = t >> 4, bc1 = (t & 15) * 8;    // 128-wide B rows br1, br1+16
    int brow = t >> 3, bcol = (t & 7) * 8;   // 64-wide B (stage B, proven pattern)

    // ================= stage A =================
    float cA[2][2][4][4];   // [nh][mi][ni][q]
    #pragma unroll
    for (int nh = 0; nh < 2; nh++)
        #pragma unroll
        for (int mi = 0; mi < 2; mi++)
            #pragma unroll
            for (int ni = 0; ni < 4; ni++)
                #pragma unroll
                for (int q = 0; q < 4; q++) cA[nh][mi][ni][q] = 0.f;

    int r0 = bm + ar, r1 = bm + ar + 64;
    const __half* Ap0 = A + (size_t)r0 * INF + ac;
    const __half* Ap1 = A + (size_t)r1 * INF + ac;
    bool ok0 = r0 < n, ok1 = r1 < n;

    uint4 av0 = make_uint4(0u,0u,0u,0u), av1 = make_uint4(0u,0u,0u,0u);
    if (ok0) av0 = *(const uint4*)Ap0;
    if (ok1) av1 = *(const uint4*)Ap1;
    uint4 bw0 = *(const uint4*)(B0 + (size_t)br1 * INF + bc1);
    uint4 bw1 = *(const uint4*)(B0 + (size_t)(br1 + 16) * INF + bc1);

    for (int k0 = 0; k0 < INF; k0 += 32) {
        __syncthreads();
        *(uint4*)&As[ar][ac]      = av0;
        *(uint4*)&As[ar + 64][ac] = av1;
        *(uint4*)&Bs[br1][bc1]      = bw0;
        *(uint4*)&Bs[br1 + 16][bc1] = bw1;
        __syncthreads();

        int kn = k0 + 32;
        if (kn < INF) {
            av0 = make_uint4(0u,0u,0u,0u); av1 = make_uint4(0u,0u,0u,0u);
            if (ok0) av0 = *(const uint4*)(Ap0 + kn);
            if (ok1) av1 = *(const uint4*)(Ap1 + kn);
            bw0 = *(const uint4*)(B0 + (size_t)(kn + br1) * INF + bc1);
            bw1 = *(const uint4*)(B0 + (size_t)(kn + br1 + 16) * INF + bc1);
        }

        #pragma unroll
        for (int ks = 0; ks < 32; ks += 16) {
            unsigned int afr[2][4], bfr[2][2][4];
            #pragma unroll
            for (int mi = 0; mi < 2; mi++) {
                unsigned int addr = smem_u32(&As[warp_m * 32 + mi * 16 + (lane & 15)][ks + (lane >> 4) * 8]);
                asm volatile("ldmatrix.sync.aligned.m8n8.x4.shared.b16 {%0,%1,%2,%3}, [%4];"
                    : "=r"(afr[mi][0]), "=r"(afr[mi][1]), "=r"(afr[mi][2]), "=r"(afr[mi][3])
                    : "r"(addr));
            }
            #pragma unroll
            for (int nh = 0; nh < 2; nh++)
                #pragma unroll
                for (int nb = 0; nb < 2; nb++) {
                    unsigned int addr = smem_u32(&Bs[ks + (lane & 15)][nh * 64 + warp_n * 32 + nb * 16 + (lane >> 4) * 8]);
                    asm volatile("ldmatrix.sync.aligned.m8n8.x4.trans.shared.b16 {%0,%1,%2,%3}, [%4];"
                        : "=r"(bfr[nh][nb][0]), "=r"(bfr[nh][nb][1]), "=r"(bfr[nh][nb][2]), "=r"(bfr[nh][nb][3])
                        : "r"(addr));
                }
            #pragma unroll
            for (int nh = 0; nh < 2; nh++)
                #pragma unroll
                for (int mi = 0; mi < 2; mi++)
                    #pragma unroll
                    for (int ni = 0; ni < 4; ni++) {
                        unsigned int b0 = bfr[nh][ni >> 1][(ni & 1) * 2 + 0];
                        unsigned int b1 = bfr[nh][ni >> 1][(ni & 1) * 2 + 1];
                        asm volatile(
                            "mma.sync.aligned.m16n8k16.row.col.f32.f16.f16.f32 "
                            "{%0,%1,%2,%3}, {%4,%5,%6,%7}, {%8,%9}, {%0,%1,%2,%3};"
                            : "+f"(cA[nh][mi][ni][0]), "+f"(cA[nh][mi][ni][1]),
                              "+f"(cA[nh][mi][ni][2]), "+f"(cA[nh][mi][ni][3])
                            : "r"(afr[mi][0]), "r"(afr[mi][1]), "r"(afr[mi][2]), "r"(afr[mi][3]),
                              "r"(b0), "r"(b1));
                    }
        }
    }

    // write XP to smem (overwrites the As alias -> must sync first)
    __syncthreads();
    #pragma unroll
    for (int mi = 0; mi < 2; mi++) {
        int rlA = warp_m * 32 + mi * 16 + (lane >> 2);
        int rlB = rlA + 8;
        #pragma unroll
        for (int nh = 0; nh < 2; nh++)
            #pragma unroll
            for (int ni = 0; ni < 4; ni++) {
                int cc = nh * 64 + warp_n * 32 + ni * 8 + (lane & 3) * 2;
                float b0 = bias[cc], b1 = bias[cc + 1];
                *(__half2*)&XPs[rlA][cc] =
                    __floats2half2_rn(cA[nh][mi][ni][0] + b0, cA[nh][mi][ni][1] + b1);
                *(__half2*)&XPs[rlB][cc] =
                    __floats2half2_rn(cA[nh][mi][ni][2] + b0, cA[nh][mi][ni][3] + b1);
            }
    }
    __syncthreads();

    // ================= stage B: 8 heads =================
    for (int h = 0; h < NH; h++) {
        float c[2][4][4];
        #pragma unroll
        for (int mi = 0; mi < 2; mi++)
            #pragma unroll
            for (int ni = 0; ni < 4; ni++)
                #pragma unroll
                for (int q = 0; q < 4; q++) c[mi][ni][q] = 0.f;

        const __half* Bp = Bc + (size_t)brow * F1 + h * 64 + bcol;
        uint4 bv = *(const uint4*)Bp;

        for (int k0 = 0; k0 < INF; k0 += 32) {
            __syncthreads();
            *(uint4*)&Bs[brow][bcol] = bv;
            __syncthreads();

            int kn = k0 + 32;
            if (kn < INF) bv = *(const uint4*)(Bp + (size_t)kn * F1);

            #pragma unroll
            for (int ks = 0; ks < 32; ks += 16) {
                unsigned int afr[2][4], bfr[2][4];
                #pragma unroll
                for (int mi = 0; mi < 2; mi++) {
                    unsigned int addr = smem_u32(&XPs[warp_m * 32 + mi * 16 + (lane & 15)][k0 + ks + (lane >> 4) * 8]);
                    asm volatile("ldmatrix.sync.aligned.m8n8.x4.shared.b16 {%0,%1,%2,%3}, [%4];"
                        : "=r"(afr[mi][0]), "=r"(afr[mi][1]), "=r"(afr[mi][2]), "=r"(afr[mi][3])
                        : "r"(addr));
                }
                #pragma unroll
                for (int nb = 0; nb < 2; nb++) {
                    unsigned int addr = smem_u32(&Bs[ks + (lane & 15)][warp_n * 32 + nb * 16 + (lane >> 4) * 8]);
                    asm volatile("ldmatrix.sync.aligned.m8n8.x4.trans.shared.b16 {%0,%1,%2,%3}, [%4];"
                        : "=r"(bfr[nb][0]), "=r"(bfr[nb][1]), "=r"(bfr[nb][2]), "=r"(bfr[nb][3])
                        : "r"(addr));
                }
                #pragma unroll
                for (int mi = 0; mi < 2; mi++)
                    #pragma unroll
                    for (int ni = 0; ni < 4; ni++) {
                        unsigned int b0 = bfr[ni >> 1][(ni & 1) * 2 + 0];
                        unsigned int b1 = bfr[ni >> 1][(ni & 1) * 2 + 1];
                        asm volatile(
                            "mma.sync.aligned.m16n8k16.row.col.f32.f16.f16.f32 "
                            "{%0,%1,%2,%3}, {%4,%5,%6,%7}, {%8,%9}, {%0,%1,%2,%3};"
                            : "+f"(c[mi][ni][0]), "+f"(c[mi][ni][1]),
                              "+f"(c[mi][ni][2]), "+f"(c[mi][ni][3])
                            : "r"(afr[mi][0]), "r"(afr[mi][1]), "r"(afr[mi][2]), "r"(afr[mi][3]),
                              "r"(b0), "r"(b1));
                    }
            }
        }

        // epilogue: h1 store + fused per-head scores (proven SCORES path)
        const float* avec = a_heads + h * 128;
        float a_s[4][2], a_d[4][2];
        #pragma unroll
        for (int ni = 0; ni < 4; ni++) {
            int colh = warp_n * 32 + ni * 8 + (lane & 3) * 2;
            float2 vs = *(const float2*)(avec + colh);
            float2 vd = *(const float2*)(avec + 64 + colh);
            a_s[ni][0] = vs.x; a_s[ni][1] = vs.y;
            a_d[ni][0] = vd.x; a_d[ni][1] = vd.y;
        }

        #pragma unroll
        for (int mi = 0; mi < 2; mi++) {
            int rA = bm + warp_m * 32 + mi * 16 + (lane >> 2);
            int rB = rA + 8;
            float psA = 0.f, pdA = 0.f, psB = 0.f, pdB = 0.f;
            #pragma unroll
            for (int ni = 0; ni < 4; ni++) {
                int ccl = warp_n * 32 + ni * 8 + (lane & 3) * 2;
                int cc = h * 64 + ccl;
                if (rA < n) *(__half2*)(C + (size_t)rA * F1 + cc) =
                    __floats2half2_rn(c[mi][ni][0], c[mi][ni][1]);
                if (rB < n) *(__half2*)(C + (size_t)rB * F1 + cc) =
                    __floats2half2_rn(c[mi][ni][2], c[mi][ni][3]);
                psA += c[mi][ni][0] * a_s[ni][0] + c[mi][ni][1] * a_s[ni][1];
                pdA += c[mi][ni][0] * a_d[ni][0] + c[mi][ni][1] * a_d[ni][1];
                psB += c[mi][ni][2] * a_s[ni][0] + c[mi][ni][3] * a_s[ni][1];
                pdB += c[mi][ni][2] * a_d[ni][0] + c[mi][ni][3] * a_d[ni][1];
            }
            #pragma unroll
            for (int off = 1; off <= 2; off <<= 1) {
                psA += __shfl_xor_sync(0xffffffffu, psA, off);
                pdA += __shfl_xor_sync(0xffffffffu, pdA, off);
                psB += __shfl_xor_sync(0xffffffffu, psB, off);
                pdB += __shfl_xor_sync(0xffffffffu, pdB, off);
            }
            if ((lane & 3) == 0) {
                if (rA < n) {
                    atomicAdd(&ssrc_arr[rA * NH + h], psA);
                    atomicAdd(&sdst_arr[rA * NH + h], pdA);
                }
                if (rB < n) {
                    atomicAdd(&ssrc_arr[rB * NH + h], psB);
                    atomicAdd(&sdst_arr[rB * NH + h], pdB);
                }
            }
        }
    }
}

// ---------------- tensor-core GEMM (GEMM3): proven kernel ----------------
template<bool HALF_OUT, bool BIAS, bool SCORES, bool STREAM_A>
__global__ void mma_gemm_kernel(const __half* __restrict__ A, const __half* __restrict__ B,
                                const float* __restrict__ bias, void* __restrict__ Cv,
                                const float* __restrict__ avec_base,
                                float* __restrict__ ssrc_arr, float* __restrict__ sdst_arr,
                                int sstride, int n, int K, int M) {
    __shared__ __half As[128][40];
    __shared__ __half Bs[32][72];
    int t = threadIdx.x;
    int lane = t & 31, wid = t >> 5;
    int warp_m = wid & 3;
    int warp_n = wid >> 2;
    int bm = blockIdx.y * 128;
    int bn = blockIdx.x * 64;

    int ar = t >> 2;
    int ac = (t & 3) * 8;
    int brow = t >> 3;
    int bcol = (t & 7) * 8;

    float c[2][4][4];
    #pragma unroll
    for (int mi = 0; mi < 2; mi++)
        #pragma unroll
        for (int ni = 0; ni < 4; ni++)
            #pragma unroll
            for (int q = 0; q < 4; q++) c[mi][ni][q] = 0.f;

    int r0 = bm + ar, r1 = bm + ar + 64;
    const __half* Ap0 = A + (size_t)r0 * K + ac;
    const __half* Ap1 = A + (size_t)r1 * K + ac;
    const __half* Bp  = B + (size_t)brow * M + bn + bcol;
    bool ok0 = r0 < n, ok1 = r1 < n;

    uint4 av0 = make_uint4(0u,0u,0u,0u), av1 = make_uint4(0u,0u,0u,0u);
    if (ok0) av0 = STREAM_A ? __ldcs((const uint4*)Ap0) : *(const uint4*)Ap0;
    if (ok1) av1 = STREAM_A ? __ldcs((const uint4*)Ap1) : *(const uint4*)Ap1;
    uint4 bv = *(const uint4*)Bp;

    for (int k0 = 0; k0 < K; k0 += 32) {
        __syncthreads();
        *(uint4*)&As[ar][ac]      = av0;
        *(uint4*)&As[ar + 64][ac] = av1;
        *(uint4*)&Bs[brow][bcol]  = bv;
        __syncthreads();

        int kn = k0 + 32;
        if (kn < K) {
            av0 = make_uint4(0u,0u,0u,0u); av1 = make_uint4(0u,0u,0u,0u);
            if (ok0) av0 = STREAM_A ? __ldcs((const uint4*)(Ap0 + kn)) : *(const uint4*)(Ap0 + kn);
            if (ok1) av1 = STREAM_A ? __ldcs((const uint4*)(Ap1 + kn)) : *(const uint4*)(Ap1 + kn);
            bv = *(const uint4*)(Bp + (size_t)kn * M);
        }

        #pragma unroll
        for (int ks = 0; ks < 32; ks += 16) {
            unsigned int afr[2][4], bfr[2][4];
            #pragma unroll
            for (int mi = 0; mi < 2; mi++) {
                unsigned int addr = smem_u32(&As[warp_m * 32 + mi * 16 + (lane & 15)][ks + (lane >> 4) * 8]);
                asm volatile("ldmatrix.sync.aligned.m8n8.x4.shared.b16 {%0,%1,%2,%3}, [%4];"
                    : "=r"(afr[mi][0]), "=r"(afr[mi][1]), "=r"(afr[mi][2]), "=r"(afr[mi][3])
                    : "r"(addr));
            }
            #pragma unroll
            for (int nb = 0; nb < 2; nb++) {
                unsigned int addr = smem_u32(&Bs[ks + (lane & 15)][warp_n * 32 + nb * 16 + (lane >> 4) * 8]);
                asm volatile("ldmatrix.sync.aligned.m8n8.x4.trans.shared.b16 {%0,%1,%2,%3}, [%4];"
                    : "=r"(bfr[nb][0]), "=r"(bfr[nb][1]), "=r"(bfr[nb][2]), "=r"(bfr[nb][3])
                    : "r"(addr));
            }
            #pragma unroll
            for (int mi = 0; mi < 2; mi++)
                #pragma unroll
                for (int ni = 0; ni < 4; ni++) {
                    unsigned int b0 = bfr[ni >> 1][(ni & 1) * 2 + 0];
                    unsigned int b1 = bfr[ni >> 1][(ni & 1) * 2 + 1];
                    asm volatile(
                        "mma.sync.aligned.m16n8k16.row.col.f32.f16.f16.f32 "
                        "{%0,%1,%2,%3}, {%4,%5,%6,%7}, {%8,%9}, {%0,%1,%2,%3};"
                        : "+f"(c[mi][ni][0]), "+f"(c[mi][ni][1]),
                          "+f"(c[mi][ni][2]), "+f"(c[mi][ni][3])
                        : "r"(afr[mi][0]), "r"(afr[mi][1]), "r"(afr[mi][2]), "r"(afr[mi][3]),
                          "r"(b0), "r"(b1));
                }
        }
    }

    int rb = bm + warp_m * 32;
    int cbw = bn + warp_n * 32;

    float a_s[4][2], a_d[4][2];
    if (SCORES) {
        const float* avec = avec_base + blockIdx.x * 128;
        #pragma unroll
        for (int ni = 0; ni < 4; ni++) {
            int colh = warp_n * 32 + ni * 8 + (lane & 3) * 2;
            float2 vs = *(const float2*)(avec + colh);
            float2 vd = *(const float2*)(avec + 64 + colh);
            a_s[ni][0] = vs.x; a_s[ni][1] = vs.y;
            a_d[ni][0] = vd.x; a_d[ni][1] = vd.y;
        }
    }

    #pragma unroll
    for (int mi = 0; mi < 2; mi++) {
        int rA = rb + mi * 16 + (lane >> 2);
        int rB = rA + 8;
        float psA = 0.f, pdA = 0.f, psB = 0.f, pdB = 0.f;
        #pragma unroll
        for (int ni = 0; ni < 4; ni++) {
            int cc = cbw + ni * 8 + (lane & 3) * 2;
            float b0 = 0.f, b1 = 0.f;
            if (BIAS) { b0 = bias[cc]; b1 = bias[cc + 1]; }
            if (HALF_OUT) {
                __half* C = (__half*)Cv;
                if (rA < n) *(__half2*)(C + (size_t)rA * M + cc) =
                    __floats2half2_rn(c[mi][ni][0] + b0, c[mi][ni][1] + b1);
                if (rB < n) *(__half2*)(C + (size_t)rB * M + cc) =
                    __floats2half2_rn(c[mi][ni][2] + b0, c[mi][ni][3] + b1);
            } else {
                float* C = (float*)Cv;
                if (rA < n) *(float2*)(C + (size_t)rA * M + cc) =
                    make_float2(c[mi][ni][0] + b0, c[mi][ni][1] + b1);
                if (rB < n) *(float2*)(C + (size_t)rB * M + cc) =
                    make_float2(c[mi][ni][2] + b0, c[mi][ni][3] + b1);
            }
            if (SCORES) {
                psA += c[mi][ni][0] * a_s[ni][0] + c[mi][ni][1] * a_s[ni][1];
                pdA += c[mi][ni][0] * a_d[ni][0] + c[mi][ni][1] * a_d[ni][1];
                psB += c[mi][ni][2] * a_s[ni][0] + c[mi][ni][3] * a_s[ni][1];
                pdB += c[mi][ni][2] * a_d[ni][0] + c[mi][ni][3] * a_d[ni][1];
            }
        }
        if (SCORES) {
            #pragma unroll
            for (int off = 1; off <= 2; off <<= 1) {
                psA += __shfl_xor_sync(0xffffffffu, psA, off);
                pdA += __shfl_xor_sync(0xffffffffu, pdA, off);
                psB += __shfl_xor_sync(0xffffffffu, psB, off);
                pdB += __shfl_xor_sync(0xffffffffu, pdB, off);
            }
            if ((lane & 3) == 0) {
                int h = blockIdx.x;
                if (rA < n) {
                    atomicAdd(&ssrc_arr[rA * sstride + h], psA);
                    atomicAdd(&sdst_arr[rA * sstride + h], pdA);
                }
                if (rB < n) {
                    atomicAdd(&ssrc_arr[rB * sstride + h], psB);
                    atomicAdd(&sdst_arr[rB * sstride + h], pdB);
                }
            }
        }
    }
}

// ---------------- layer-1 aggregation: warp per node (fp16 gather, fp32 accum) ----------------
__global__ void agg1_kernel() {
    int node = (blockIdx.x * blockDim.x + threadIdx.x) >> 5;
    if (node >= Nn) return;
    int lane = threadIdx.x & 31;
    int hl   = lane & 7;
    int hsel = lane >> 4;

    float ssrc = g_ssrc1[node * NH + hl];
    int beg = g_rowptr[node], end = g_rowptr[node + 1];

    float4 acc[4];
    float  rs[4];
    #pragma unroll
    for (int k = 0; k < 4; k++) { acc[k] = make_float4(0.f,0.f,0.f,0.f); rs[k] = 0.f; }

    for (int j = beg; j < end; j++) {
        int d = g_dst[j];
        float sc = ssrc + g_sdst1[d * NH + hl];
        float lr = sc > 0.f ? sc : ALPHA * sc;
        float w8 = __expf(-lr);
        const __half* hp = g_h1 + (size_t)d * F1;
        #pragma unroll
        for (int k = 0; k < 4; k++) {
            float w = __shfl_sync(0xffffffffu, w8, 2 * k + hsel);
            float4 v = load_half4_cg(hp + k * 128 + lane * 4);
            acc[k].x += w * v.x; acc[k].y += w * v.y;
            acc[k].z += w * v.z; acc[k].w += w * v.w;
            rs[k] += w;
        }
    }

    __half* outp = g_out1 + (size_t)node * F1;
    #pragma unroll
    for (int k = 0; k < 4; k++) {
        float inv = 1.f / (rs[k] + 1e-16f);
        float4 o;
        o.x = acc[k].x * inv; o.y = acc[k].y * inv;
        o.z = acc[k].z * inv; o.w = acc[k].w * inv;
        o.x = o.x > 0.f ? o.x : expm1f(o.x);
        o.y = o.y > 0.f ? o.y : expm1f(o.y);
        o.z = o.z > 0.f ? o.z : expm1f(o.z);
        o.w = o.w > 0.f ? o.w : expm1f(o.w);
        __half2 ha = __floats2half2_rn(o.x, o.y);
        __half2 hb = __floats2half2_rn(o.z, o.w);
        uint2 u;
        u.x = *(unsigned int*)&ha;
        u.y = *(unsigned int*)&hb;
        __stcs((uint2*)(outp + k * 128 + lane * 4), u);
    }
}

// ---------------- layer-2 aggregation + softmax: warp per node (fp16 h2) ----------------
__global__ void agg2_kernel(float* __restrict__ out) {
    int node = (blockIdx.x * blockDim.x + threadIdx.x) >> 5;
    if (node >= Nn) return;
    int lane = threadIdx.x & 31;

    float ss = g_ssrc2[node];
    int beg = g_rowptr[node], end = g_rowptr[node + 1];
    float a0 = 0.f, a1 = 0.f, rs = 0.f;
    for (int j = beg; j < end; j++) {
        int d = g_dst[j];
        float sc = ss + g_sdst2[d];
        float lr = sc > 0.f ? sc : ALPHA * sc;
        float w = __expf(-lr);
        const __half2* hp = (const __half2*)(g_h2h + (size_t)d * OUTF);
        unsigned int uu = __ldcg((const unsigned int*)(hp + lane));
        float2 f = __half22float2(*(__half2*)&uu);
        a0 += w * f.x;
        a1 += w * f.y;
        rs += w;
    }
    float inv = 1.f / (rs + 1e-16f);
    float v0 = a0 * inv, v1 = a1 * inv;

    float m = fmaxf(v0, v1);
    #pragma unroll
    for (int off = 16; off; off >>= 1) m = fmaxf(m, __shfl_xor_sync(0xffffffffu, m, off));
    float e0 = __expf(v0 - m), e1 = __expf(v1 - m);
    float s = e0 + e1;
    #pragma unroll
    for (int off = 16; off; off >>= 1) s += __shfl_xor_sync(0xffffffffu, s, off);
    float invs = 1.f / s;
    *(float2*)(out + (size_t)node * OUTF + lane * 2) = make_float2(e0 * invs, e1 * invs);
}

// ---------------- launch ----------------
extern "C" void kernel_launch(void* const* d_in, const int* in_sizes, int n_in,
                              void* d_out, int out_size) {
    const float* x       = (const float*)d_in[0];
    const int*   edges   = (const int*)  d_in[1];
    const float* W0      = (const float*)d_in[2];
    const float* b0      = (const float*)d_in[3];
    const float* W_heads = (const float*)d_in[4];
    const float* a_heads = (const float*)d_in[5];
    const float* W_end   = (const float*)d_in[6];
    const float* a_end   = (const float*)d_in[7];
    float* out = (float*)d_out;
    const int* src = edges;
    const int* dst = edges + Ee;

    __half *p_xh, *p_h1, *p_out1, *p_h2h, *p_W0h, *p_Wcath, *p_Wendh;
    float  *p_ssrc1, *p_sdst1, *p_ssrc2, *p_sdst2;
    cudaGetSymbolAddress((void**)&p_xh,    g_x_h);
    cudaGetSymbolAddress((void**)&p_h1,    g_h1);
    cudaGetSymbolAddress((void**)&p_out1,  g_out1);
    cudaGetSymbolAddress((void**)&p_h2h,   g_h2h);
    cudaGetSymbolAddress((void**)&p_W0h,   g_W0h);
    cudaGetSymbolAddress((void**)&p_Wcath, g_Wcat_h);
    cudaGetSymbolAddress((void**)&p_Wendh, g_Wend_h);
    cudaGetSymbolAddress((void**)&p_ssrc1, g_ssrc1);
    cudaGetSymbolAddress((void**)&p_sdst1, g_sdst1);
    cudaGetSymbolAddress((void**)&p_ssrc2, g_ssrc2);
    cudaGetSymbolAddress((void**)&p_sdst2, g_sdst2);

    // Side stream + fork/join events (host-side objects only; created once).
    static cudaStream_t s_csr = nullptr;
    static cudaEvent_t  ev_fork = nullptr, ev_join = nullptr;
    if (s_csr == nullptr) {
        cudaStreamCreateWithFlags(&s_csr, cudaStreamNonBlocking);
        cudaEventCreateWithFlags(&ev_fork, cudaEventDisableTiming);
        cudaEventCreateWithFlags(&ev_join, cudaEventDisableTiming);
    }

    // ---- fork: CSR chain on side stream ----
    cudaEventRecord(ev_fork, 0);
    cudaStreamWaitEvent(s_csr, ev_fork, 0);
    zero_counts_kernel<<<(Nn + 255) / 256, 256, 0, s_csr>>>();
    count_kernel<<<(Ee + 255) / 256, 256, 0, s_csr>>>(src);
    scan_block_kernel<<<NB_SCAN, 1024, 0, s_csr>>>();
    scan_top_kernel<<<1, 128, 0, s_csr>>>();
    scan_add_kernel<<<(Nn + 255) / 256, 256, 0, s_csr>>>();
    scatter_kernel<<<(Ee + 255) / 256, 256, 0, s_csr>>>(src, dst);
    cudaEventRecord(ev_join, s_csr);

    // ---- main stream: dense chain (independent of CSR until agg1) ----
    f2h_kernel<<<(Nn * INF / 4 + 255) / 256, 256>>>(x, p_xh, Nn * INF);
    prep_kernel<<<(Nn * NH + 255) / 256, 256>>>(W0, W_end, W_heads);

    const int GY = (Nn + 127) / 128;   // 782

    // FUSED: xp = x@W0+b0 (smem-resident) ; h1 = xp@Wcat + fused s1 scores
    fused_g12_kernel<<<GY, 256>>>(p_xh, p_W0h, b0, p_Wcath, a_heads,
                                  p_h1, p_ssrc1, p_sdst1, Nn);

    // ---- join: agg1 needs both the CSR and the dense chain ----
    cudaStreamWaitEvent(0, ev_join, 0);

    // layer-1 aggregation + ELU -> out1 [N,512] (fp16)
    agg1_kernel<<<(Nn + 7) / 8, 256>>>();
    // h2 = out1 @ W_end  (fp16 out; A read-once -> streaming) + fused s2 scores
    mma_gemm_kernel<true, false, true, true><<<dim3(OUTF / 64, GY), 256>>>(
        p_out1, p_Wendh, nullptr, p_h2h, a_end, p_ssrc2, p_sdst2, 1, Nn, F1, OUTF);
    // layer-2 aggregation + softmax -> output
    agg2_kernel<<<(Nn + 7) / 8, 256>>>(out);
}

// round 17
// speedup vs baseline: 1.1957x; 1.0546x over previous
#include <cuda_runtime.h>
#include <cuda_fp16.h>
#include <math.h>
#include <stdint.h>

// Problem constants (fixed by the reference)
#define Nn   100000
#define Ee   1600000
#define INF  128
#define HIDF 64
#define NH   8
#define F1   512      // NH*HIDF
#define OUTF 64
#define ALPHA 0.2f
#define NB_SCAN ((Nn + 1023) / 1024)   // 98

// ---------------- device scratch (no allocations allowed) ----------------
__device__ __half g_h1[(size_t)Nn * F1];          // 102.4 MB (~fits L2)
__device__ __half g_out1[(size_t)Nn * F1];        // 102.4 MB
__device__ __half g_h2h[Nn * OUTF];               // 12.8 MB (L2-resident)
__device__ __half g_W0h[INF * INF];
__device__ __half g_Wcat_h[INF * F1];             // repacked head weights (fp16)
__device__ __half g_Wend_h[F1 * OUTF];
__device__ float  g_ssrc1[Nn * NH];
__device__ float  g_sdst1[Nn * NH];
__device__ float  g_ssrc2[Nn];
__device__ float  g_sdst2[Nn];
__device__ int    g_counts[Nn];
__device__ int    g_fill[Nn];
__device__ int    g_rowptr[Nn + 1];
__device__ int    g_dst[Ee];
__device__ int    g_blksums[128];

// ---------------- fp16 helpers ----------------
// L2-only load (skip L1 fill): for random gathers with no L1 reuse.
__device__ __forceinline__ float4 load_half4_cg(const __half* p) {
    uint2 u = __ldcg((const uint2*)p);
    __half2 a = *(__half2*)&u.x;
    __half2 b = *(__half2*)&u.y;
    float2 fa = __half22float2(a), fb = __half22float2(b);
    return make_float4(fa.x, fa.y, fb.x, fb.y);
}
__device__ __forceinline__ unsigned int smem_u32(const void* p) {
    return (unsigned int)__cvta_generic_to_shared(p);
}
// 8 fp32 -> 8 fp16 (packed uint4), streaming loads (x is read exactly once).
__device__ __forceinline__ uint4 load_f32x8_as_h8(const float* p) {
    float4 f0 = __ldcs((const float4*)p);
    float4 f1 = __ldcs((const float4*)p + 1);
    __half2 h0 = __floats2half2_rn(f0.x, f0.y);
    __half2 h1 = __floats2half2_rn(f0.z, f0.w);
    __half2 h2 = __floats2half2_rn(f1.x, f1.y);
    __half2 h3 = __floats2half2_rn(f1.z, f1.w);
    uint4 r;
    r.x = *(unsigned int*)&h0; r.y = *(unsigned int*)&h1;
    r.z = *(unsigned int*)&h2; r.w = *(unsigned int*)&h3;
    return r;
}

// ---------------- CSR-stream zero ----------------
__global__ void zero_counts_kernel() {
    int i = blockIdx.x * blockDim.x + threadIdx.x;
    if (i < Nn) { g_counts[i] = 0; g_fill[i] = 0; }
}

__global__ void count_kernel(const int* __restrict__ src) {
    int e = blockIdx.x * blockDim.x + threadIdx.x;
    if (e < Ee) atomicAdd(&g_counts[src[e]], 1);
}

__global__ void scan_block_kernel() {
    __shared__ int sh[1024];
    int i = blockIdx.x * 1024 + threadIdx.x;
    int v = (i < Nn) ? g_counts[i] : 0;
    sh[threadIdx.x] = v;
    __syncthreads();
    #pragma unroll
    for (int off = 1; off < 1024; off <<= 1) {
        int t = (threadIdx.x >= off) ? sh[threadIdx.x - off] : 0;
        __syncthreads();
        sh[threadIdx.x] += t;
        __syncthreads();
    }
    if (i < Nn) g_rowptr[i] = sh[threadIdx.x] - v;   // exclusive within block
    if (threadIdx.x == 1023) g_blksums[blockIdx.x] = sh[1023];
}

__global__ void scan_top_kernel() {
    __shared__ int sh[128];
    int i = threadIdx.x;
    int v = (i < NB_SCAN) ? g_blksums[i] : 0;
    sh[i] = v;
    __syncthreads();
    #pragma unroll
    for (int off = 1; off < 128; off <<= 1) {
        int t = (i >= off) ? sh[i - off] : 0;
        __syncthreads();
        sh[i] += t;
        __syncthreads();
    }
    if (i < NB_SCAN) g_blksums[i] = sh[i] - v;   // exclusive
}

__global__ void scan_add_kernel() {
    int i = blockIdx.x * blockDim.x + threadIdx.x;
    if (i < Nn) g_rowptr[i] += g_blksums[i >> 10];
    if (i == 0) g_rowptr[Nn] = Ee;
}

__global__ void scatter_kernel(const int* __restrict__ src, const int* __restrict__ dst) {
    int e = blockIdx.x * blockDim.x + threadIdx.x;
    if (e < Ee) {
        int s = src[e];
        int pos = g_rowptr[s] + atomicAdd(&g_fill[s], 1);
        g_dst[pos] = dst[e];
    }
}

// ---------------- prep: weight conversions + score zeroing ----------------
__global__ void prep_kernel(const float* __restrict__ W0,
                            const float* __restrict__ W_end,
                            const float* __restrict__ W_heads) {
    int t = blockIdx.x * blockDim.x + threadIdx.x;
    if (t < INF * INF) g_W0h[t] = __float2half(W0[t]);
    if (t < F1 * OUTF) g_Wend_h[t] = __float2half(W_end[t]);
    if (t < INF * F1) {
        int i = t / F1;
        int c = t - i * F1;
        int h = c >> 6;
        int j = c & 63;
        g_Wcat_h[t] = __float2half(W_heads[(h * INF + i) * HIDF + j]);
    }
    if (t < Nn) { g_ssrc2[t] = 0.f; g_sdst2[t] = 0.f; }
    if (t < Nn * NH) { g_ssrc1[t] = 0.f; g_sdst1[t] = 0.f; }
}

// ---------------- FUSED GEMM1+GEMM2 ----------------
// Stage A: XP[128,128] = x @ W0 + b0  (x loaded fp32, converted in-register;
//          fp32 acc, fp16 into smem — bit-identical to the f2h+GEMM path)
// Stage B: per head h: h1[:,h*64..] = XP @ Wcat[:,h*64..] + fused s1 scores.
__global__ void fused_g12_kernel(const float* __restrict__ A,     // x [n,128] fp32
                                 const __half* __restrict__ B0,   // W0h [128,128]
                                 const float* __restrict__ bias,  // b0
                                 const __half* __restrict__ Bc,   // Wcat_h [128,512]
                                 const float* __restrict__ a_heads,
                                 __half* __restrict__ C,          // h1 [n,512]
                                 float* __restrict__ ssrc_arr,
                                 float* __restrict__ sdst_arr,
                                 int n) {
    __shared__ __half XPs[128][136];  // 34816 B; row stride 272 B -> conflict-free ldmatrix
    __shared__ __half Bs[32][136];    // 8704 B; used 128-wide (stage A) / 64-wide (stage B)
    __half (*As)[40] = (__half (*)[40])XPs;   // alias: As dead before XPs is written

    int t = threadIdx.x;
    int lane = t & 31, wid = t >> 5;
    int warp_m = wid & 3;             // 32-row slab
    int warp_n = wid >> 2;            // 32-col slab (within each 64-col half/head)
    int bm = blockIdx.x * 128;

    // staging indices
    int ar = t >> 2, ac = (t & 3) * 8;       // A tile (proven pattern)
    int br1 = t >> 4, bc1 = (t & 15) * 8;    // 128-wide B rows br1, br1+16
    int brow = t >> 3, bcol = (t & 7) * 8;   // 64-wide B (stage B, proven pattern)

    // ================= stage A =================
    float cA[2][2][4][4];   // [nh][mi][ni][q]
    #pragma unroll
    for (int nh = 0; nh < 2; nh++)
        #pragma unroll
        for (int mi = 0; mi < 2; mi++)
            #pragma unroll
            for (int ni = 0; ni < 4; ni++)
                #pragma unroll
                for (int q = 0; q < 4; q++) cA[nh][mi][ni][q] = 0.f;

    int r0 = bm + ar, r1 = bm + ar + 64;
    const float* Ap0 = A + (size_t)r0 * INF + ac;
    const float* Ap1 = A + (size_t)r1 * INF + ac;
    bool ok0 = r0 < n, ok1 = r1 < n;

    uint4 av0 = make_uint4(0u,0u,0u,0u), av1 = make_uint4(0u,0u,0u,0u);
    if (ok0) av0 = load_f32x8_as_h8(Ap0);
    if (ok1) av1 = load_f32x8_as_h8(Ap1);
    uint4 bw0 = *(const uint4*)(B0 + (size_t)br1 * INF + bc1);
    uint4 bw1 = *(const uint4*)(B0 + (size_t)(br1 + 16) * INF + bc1);

    for (int k0 = 0; k0 < INF; k0 += 32) {
        __syncthreads();
        *(uint4*)&As[ar][ac]      = av0;
        *(uint4*)&As[ar + 64][ac] = av1;
        *(uint4*)&Bs[br1][bc1]      = bw0;
        *(uint4*)&Bs[br1 + 16][bc1] = bw1;
        __syncthreads();

        int kn = k0 + 32;
        if (kn < INF) {
            av0 = make_uint4(0u,0u,0u,0u); av1 = make_uint4(0u,0u,0u,0u);
            if (ok0) av0 = load_f32x8_as_h8(Ap0 + kn);
            if (ok1) av1 = load_f32x8_as_h8(Ap1 + kn);
            bw0 = *(const uint4*)(B0 + (size_t)(kn + br1) * INF + bc1);
            bw1 = *(const uint4*)(B0 + (size_t)(kn + br1 + 16) * INF + bc1);
        }

        #pragma unroll
        for (int ks = 0; ks < 32; ks += 16) {
            unsigned int afr[2][4], bfr[2][2][4];
            #pragma unroll
            for (int mi = 0; mi < 2; mi++) {
                unsigned int addr = smem_u32(&As[warp_m * 32 + mi * 16 + (lane & 15)][ks + (lane >> 4) * 8]);
                asm volatile("ldmatrix.sync.aligned.m8n8.x4.shared.b16 {%0,%1,%2,%3}, [%4];"
                    : "=r"(afr[mi][0]), "=r"(afr[mi][1]), "=r"(afr[mi][2]), "=r"(afr[mi][3])
                    : "r"(addr));
            }
            #pragma unroll
            for (int nh = 0; nh < 2; nh++)
                #pragma unroll
                for (int nb = 0; nb < 2; nb++) {
                    unsigned int addr = smem_u32(&Bs[ks + (lane & 15)][nh * 64 + warp_n * 32 + nb * 16 + (lane >> 4) * 8]);
                    asm volatile("ldmatrix.sync.aligned.m8n8.x4.trans.shared.b16 {%0,%1,%2,%3}, [%4];"
                        : "=r"(bfr[nh][nb][0]), "=r"(bfr[nh][nb][1]), "=r"(bfr[nh][nb][2]), "=r"(bfr[nh][nb][3])
                        : "r"(addr));
                }
            #pragma unroll
            for (int nh = 0; nh < 2; nh++)
                #pragma unroll
                for (int mi = 0; mi < 2; mi++)
                    #pragma unroll
                    for (int ni = 0; ni < 4; ni++) {
                        unsigned int b0 = bfr[nh][ni >> 1][(ni & 1) * 2 + 0];
                        unsigned int b1 = bfr[nh][ni >> 1][(ni & 1) * 2 + 1];
                        asm volatile(
                            "mma.sync.aligned.m16n8k16.row.col.f32.f16.f16.f32 "
                            "{%0,%1,%2,%3}, {%4,%5,%6,%7}, {%8,%9}, {%0,%1,%2,%3};"
                            : "+f"(cA[nh][mi][ni][0]), "+f"(cA[nh][mi][ni][1]),
                              "+f"(cA[nh][mi][ni][2]), "+f"(cA[nh][mi][ni][3])
                            : "r"(afr[mi][0]), "r"(afr[mi][1]), "r"(afr[mi][2]), "r"(afr[mi][3]),
                              "r"(b0), "r"(b1));
                    }
        }
    }

    // write XP to smem (overwrites the As alias -> must sync first)
    __syncthreads();
    #pragma unroll
    for (int mi = 0; mi < 2; mi++) {
        int rlA = warp_m * 32 + mi * 16 + (lane >> 2);
        int rlB = rlA + 8;
        #pragma unroll
        for (int nh = 0; nh < 2; nh++)
            #pragma unroll
            for (int ni = 0; ni < 4; ni++) {
                int cc = nh * 64 + warp_n * 32 + ni * 8 + (lane & 3) * 2;
                float b0 = bias[cc], b1 = bias[cc + 1];
                *(__half2*)&XPs[rlA][cc] =
                    __floats2half2_rn(cA[nh][mi][ni][0] + b0, cA[nh][mi][ni][1] + b1);
                *(__half2*)&XPs[rlB][cc] =
                    __floats2half2_rn(cA[nh][mi][ni][2] + b0, cA[nh][mi][ni][3] + b1);
            }
    }
    __syncthreads();

    // ================= stage B: 8 heads =================
    for (int h = 0; h < NH; h++) {
        float c[2][4][4];
        #pragma unroll
        for (int mi = 0; mi < 2; mi++)
            #pragma unroll
            for (int ni = 0; ni < 4; ni++)
                #pragma unroll
                for (int q = 0; q < 4; q++) c[mi][ni][q] = 0.f;

        const __half* Bp = Bc + (size_t)brow * F1 + h * 64 + bcol;
        uint4 bv = *(const uint4*)Bp;

        for (int k0 = 0; k0 < INF; k0 += 32) {
            __syncthreads();
            *(uint4*)&Bs[brow][bcol] = bv;
            __syncthreads();

            int kn = k0 + 32;
            if (kn < INF) bv = *(const uint4*)(Bp + (size_t)kn * F1);

            #pragma unroll
            for (int ks = 0; ks < 32; ks += 16) {
                unsigned int afr[2][4], bfr[2][4];
                #pragma unroll
                for (int mi = 0; mi < 2; mi++) {
                    unsigned int addr = smem_u32(&XPs[warp_m * 32 + mi * 16 + (lane & 15)][k0 + ks + (lane >> 4) * 8]);
                    asm volatile("ldmatrix.sync.aligned.m8n8.x4.shared.b16 {%0,%1,%2,%3}, [%4];"
                        : "=r"(afr[mi][0]), "=r"(afr[mi][1]), "=r"(afr[mi][2]), "=r"(afr[mi][3])
                        : "r"(addr));
                }
                #pragma unroll
                for (int nb = 0; nb < 2; nb++) {
                    unsigned int addr = smem_u32(&Bs[ks + (lane & 15)][warp_n * 32 + nb * 16 + (lane >> 4) * 8]);
                    asm volatile("ldmatrix.sync.aligned.m8n8.x4.trans.shared.b16 {%0,%1,%2,%3}, [%4];"
                        : "=r"(bfr[nb][0]), "=r"(bfr[nb][1]), "=r"(bfr[nb][2]), "=r"(bfr[nb][3])
                        : "r"(addr));
                }
                #pragma unroll
                for (int mi = 0; mi < 2; mi++)
                    #pragma unroll
                    for (int ni = 0; ni < 4; ni++) {
                        unsigned int b0 = bfr[ni >> 1][(ni & 1) * 2 + 0];
                        unsigned int b1 = bfr[ni >> 1][(ni & 1) * 2 + 1];
                        asm volatile(
                            "mma.sync.aligned.m16n8k16.row.col.f32.f16.f16.f32 "
                            "{%0,%1,%2,%3}, {%4,%5,%6,%7}, {%8,%9}, {%0,%1,%2,%3};"
                            : "+f"(c[mi][ni][0]), "+f"(c[mi][ni][1]),
                              "+f"(c[mi][ni][2]), "+f"(c[mi][ni][3])
                            : "r"(afr[mi][0]), "r"(afr[mi][1]), "r"(afr[mi][2]), "r"(afr[mi][3]),
                              "r"(b0), "r"(b1));
                    }
            }
        }

        // epilogue: h1 store + fused per-head scores (proven SCORES path)
        const float* avec = a_heads + h * 128;
        float a_s[4][2], a_d[4][2];
        #pragma unroll
        for (int ni = 0; ni < 4; ni++) {
            int colh = warp_n * 32 + ni * 8 + (lane & 3) * 2;
            float2 vs = *(const float2*)(avec + colh);
            float2 vd = *(const float2*)(avec + 64 + colh);
            a_s[ni][0] = vs.x; a_s[ni][1] = vs.y;
            a_d[ni][0] = vd.x; a_d[ni][1] = vd.y;
        }

        #pragma unroll
        for (int mi = 0; mi < 2; mi++) {
            int rA = bm + warp_m * 32 + mi * 16 + (lane >> 2);
            int rB = rA + 8;
            float psA = 0.f, pdA = 0.f, psB = 0.f, pdB = 0.f;
            #pragma unroll
            for (int ni = 0; ni < 4; ni++) {
                int ccl = warp_n * 32 + ni * 8 + (lane & 3) * 2;
                int cc = h * 64 + ccl;
                if (rA < n) *(__half2*)(C + (size_t)rA * F1 + cc) =
                    __floats2half2_rn(c[mi][ni][0], c[mi][ni][1]);
                if (rB < n) *(__half2*)(C + (size_t)rB * F1 + cc) =
                    __floats2half2_rn(c[mi][ni][2], c[mi][ni][3]);
                psA += c[mi][ni][0] * a_s[ni][0] + c[mi][ni][1] * a_s[ni][1];
                pdA += c[mi][ni][0] * a_d[ni][0] + c[mi][ni][1] * a_d[ni][1];
                psB += c[mi][ni][2] * a_s[ni][0] + c[mi][ni][3] * a_s[ni][1];
                pdB += c[mi][ni][2] * a_d[ni][0] + c[mi][ni][3] * a_d[ni][1];
            }
            #pragma unroll
            for (int off = 1; off <= 2; off <<= 1) {
                psA += __shfl_xor_sync(0xffffffffu, psA, off);
                pdA += __shfl_xor_sync(0xffffffffu, pdA, off);
                psB += __shfl_xor_sync(0xffffffffu, psB, off);
                pdB += __shfl_xor_sync(0xffffffffu, pdB, off);
            }
            if ((lane & 3) == 0) {
                if (rA < n) {
                    atomicAdd(&ssrc_arr[rA * NH + h], psA);
                    atomicAdd(&sdst_arr[rA * NH + h], pdA);
                }
                if (rB < n) {
                    atomicAdd(&ssrc_arr[rB * NH + h], psB);
                    atomicAdd(&sdst_arr[rB * NH + h], pdB);
                }
            }
        }
    }
}

// ---------------- tensor-core GEMM (GEMM3): proven kernel ----------------
template<bool HALF_OUT, bool BIAS, bool SCORES, bool STREAM_A>
__global__ void mma_gemm_kernel(const __half* __restrict__ A, const __half* __restrict__ B,
                                const float* __restrict__ bias, void* __restrict__ Cv,
                                const float* __restrict__ avec_base,
                                float* __restrict__ ssrc_arr, float* __restrict__ sdst_arr,
                                int sstride, int n, int K, int M) {
    __shared__ __half As[128][40];
    __shared__ __half Bs[32][72];
    int t = threadIdx.x;
    int lane = t & 31, wid = t >> 5;
    int warp_m = wid & 3;
    int warp_n = wid >> 2;
    int bm = blockIdx.y * 128;
    int bn = blockIdx.x * 64;

    int ar = t >> 2;
    int ac = (t & 3) * 8;
    int brow = t >> 3;
    int bcol = (t & 7) * 8;

    float c[2][4][4];
    #pragma unroll
    for (int mi = 0; mi < 2; mi++)
        #pragma unroll
        for (int ni = 0; ni < 4; ni++)
            #pragma unroll
            for (int q = 0; q < 4; q++) c[mi][ni][q] = 0.f;

    int r0 = bm + ar, r1 = bm + ar + 64;
    const __half* Ap0 = A + (size_t)r0 * K + ac;
    const __half* Ap1 = A + (size_t)r1 * K + ac;
    const __half* Bp  = B + (size_t)brow * M + bn + bcol;
    bool ok0 = r0 < n, ok1 = r1 < n;

    uint4 av0 = make_uint4(0u,0u,0u,0u), av1 = make_uint4(0u,0u,0u,0u);
    if (ok0) av0 = STREAM_A ? __ldcs((const uint4*)Ap0) : *(const uint4*)Ap0;
    if (ok1) av1 = STREAM_A ? __ldcs((const uint4*)Ap1) : *(const uint4*)Ap1;
    uint4 bv = *(const uint4*)Bp;

    for (int k0 = 0; k0 < K; k0 += 32) {
        __syncthreads();
        *(uint4*)&As[ar][ac]      = av0;
        *(uint4*)&As[ar + 64][ac] = av1;
        *(uint4*)&Bs[brow][bcol]  = bv;
        __syncthreads();

        int kn = k0 + 32;
        if (kn < K) {
            av0 = make_uint4(0u,0u,0u,0u); av1 = make_uint4(0u,0u,0u,0u);
            if (ok0) av0 = STREAM_A ? __ldcs((const uint4*)(Ap0 + kn)) : *(const uint4*)(Ap0 + kn);
            if (ok1) av1 = STREAM_A ? __ldcs((const uint4*)(Ap1 + kn)) : *(const uint4*)(Ap1 + kn);
            bv = *(const uint4*)(Bp + (size_t)kn * M);
        }

        #pragma unroll
        for (int ks = 0; ks < 32; ks += 16) {
            unsigned int afr[2][4], bfr[2][4];
            #pragma unroll
            for (int mi = 0; mi < 2; mi++) {
                unsigned int addr = smem_u32(&As[warp_m * 32 + mi * 16 + (lane & 15)][ks + (lane >> 4) * 8]);
                asm volatile("ldmatrix.sync.aligned.m8n8.x4.shared.b16 {%0,%1,%2,%3}, [%4];"
                    : "=r"(afr[mi][0]), "=r"(afr[mi][1]), "=r"(afr[mi][2]), "=r"(afr[mi][3])
                    : "r"(addr));
            }
            #pragma unroll
            for (int nb = 0; nb < 2; nb++) {
                unsigned int addr = smem_u32(&Bs[ks + (lane & 15)][warp_n * 32 + nb * 16 + (lane >> 4) * 8]);
                asm volatile("ldmatrix.sync.aligned.m8n8.x4.trans.shared.b16 {%0,%1,%2,%3}, [%4];"
                    : "=r"(bfr[nb][0]), "=r"(bfr[nb][1]), "=r"(bfr[nb][2]), "=r"(bfr[nb][3])
                    : "r"(addr));
            }
            #pragma unroll
            for (int mi = 0; mi < 2; mi++)
                #pragma unroll
                for (int ni = 0; ni < 4; ni++) {
                    unsigned int b0 = bfr[ni >> 1][(ni & 1) * 2 + 0];
                    unsigned int b1 = bfr[ni >> 1][(ni & 1) * 2 + 1];
                    asm volatile(
                        "mma.sync.aligned.m16n8k16.row.col.f32.f16.f16.f32 "
                        "{%0,%1,%2,%3}, {%4,%5,%6,%7}, {%8,%9}, {%0,%1,%2,%3};"
                        : "+f"(c[mi][ni][0]), "+f"(c[mi][ni][1]),
                          "+f"(c[mi][ni][2]), "+f"(c[mi][ni][3])
                        : "r"(afr[mi][0]), "r"(afr[mi][1]), "r"(afr[mi][2]), "r"(afr[mi][3]),
                          "r"(b0), "r"(b1));
                }
        }
    }

    int rb = bm + warp_m * 32;
    int cbw = bn + warp_n * 32;

    float a_s[4][2], a_d[4][2];
    if (SCORES) {
        const float* avec = avec_base + blockIdx.x * 128;
        #pragma unroll
        for (int ni = 0; ni < 4; ni++) {
            int colh = warp_n * 32 + ni * 8 + (lane & 3) * 2;
            float2 vs = *(const float2*)(avec + colh);
            float2 vd = *(const float2*)(avec + 64 + colh);
            a_s[ni][0] = vs.x; a_s[ni][1] = vs.y;
            a_d[ni][0] = vd.x; a_d[ni][1] = vd.y;
        }
    }

    #pragma unroll
    for (int mi = 0; mi < 2; mi++) {
        int rA = rb + mi * 16 + (lane >> 2);
        int rB = rA + 8;
        float psA = 0.f, pdA = 0.f, psB = 0.f, pdB = 0.f;
        #pragma unroll
        for (int ni = 0; ni < 4; ni++) {
            int cc = cbw + ni * 8 + (lane & 3) * 2;
            float b0 = 0.f, b1 = 0.f;
            if (BIAS) { b0 = bias[cc]; b1 = bias[cc + 1]; }
            if (HALF_OUT) {
                __half* C = (__half*)Cv;
                if (rA < n) *(__half2*)(C + (size_t)rA * M + cc) =
                    __floats2half2_rn(c[mi][ni][0] + b0, c[mi][ni][1] + b1);
                if (rB < n) *(__half2*)(C + (size_t)rB * M + cc) =
                    __floats2half2_rn(c[mi][ni][2] + b0, c[mi][ni][3] + b1);
            } else {
                float* C = (float*)Cv;
                if (rA < n) *(float2*)(C + (size_t)rA * M + cc) =
                    make_float2(c[mi][ni][0] + b0, c[mi][ni][1] + b1);
                if (rB < n) *(float2*)(C + (size_t)rB * M + cc) =
                    make_float2(c[mi][ni][2] + b0, c[mi][ni][3] + b1);
            }
            if (SCORES) {
                psA += c[mi][ni][0] * a_s[ni][0] + c[mi][ni][1] * a_s[ni][1];
                pdA += c[mi][ni][0] * a_d[ni][0] + c[mi][ni][1] * a_d[ni][1];
                psB += c[mi][ni][2] * a_s[ni][0] + c[mi][ni][3] * a_s[ni][1];
                pdB += c[mi][ni][2] * a_d[ni][0] + c[mi][ni][3] * a_d[ni][1];
            }
        }
        if (SCORES) {
            #pragma unroll
            for (int off = 1; off <= 2; off <<= 1) {
                psA += __shfl_xor_sync(0xffffffffu, psA, off);
                pdA += __shfl_xor_sync(0xffffffffu, pdA, off);
                psB += __shfl_xor_sync(0xffffffffu, psB, off);
                pdB += __shfl_xor_sync(0xffffffffu, pdB, off);
            }
            if ((lane & 3) == 0) {
                int h = blockIdx.x;
                if (rA < n) {
                    atomicAdd(&ssrc_arr[rA * sstride + h], psA);
                    atomicAdd(&sdst_arr[rA * sstride + h], pdA);
                }
                if (rB < n) {
                    atomicAdd(&ssrc_arr[rB * sstride + h], psB);
                    atomicAdd(&sdst_arr[rB * sstride + h], pdB);
                }
            }
        }
    }
}

// ---------------- layer-1 aggregation: warp per node (fp16 gather, fp32 accum) ----------------
__global__ void agg1_kernel() {
    int node = (blockIdx.x * blockDim.x + threadIdx.x) >> 5;
    if (node >= Nn) return;
    int lane = threadIdx.x & 31;
    int hl   = lane & 7;
    int hsel = lane >> 4;

    float ssrc = g_ssrc1[node * NH + hl];
    int beg = g_rowptr[node], end = g_rowptr[node + 1];

    float4 acc[4];
    float  rs[4];
    #pragma unroll
    for (int k = 0; k < 4; k++) { acc[k] = make_float4(0.f,0.f,0.f,0.f); rs[k] = 0.f; }

    for (int j = beg; j < end; j++) {
        int d = g_dst[j];
        float sc = ssrc + g_sdst1[d * NH + hl];
        float lr = sc > 0.f ? sc : ALPHA * sc;
        float w8 = __expf(-lr);
        const __half* hp = g_h1 + (size_t)d * F1;
        #pragma unroll
        for (int k = 0; k < 4; k++) {
            float w = __shfl_sync(0xffffffffu, w8, 2 * k + hsel);
            float4 v = load_half4_cg(hp + k * 128 + lane * 4);
            acc[k].x += w * v.x; acc[k].y += w * v.y;
            acc[k].z += w * v.z; acc[k].w += w * v.w;
            rs[k] += w;
        }
    }

    __half* outp = g_out1 + (size_t)node * F1;
    #pragma unroll
    for (int k = 0; k < 4; k++) {
        float inv = 1.f / (rs[k] + 1e-16f);
        float4 o;
        o.x = acc[k].x * inv; o.y = acc[k].y * inv;
        o.z = acc[k].z * inv; o.w = acc[k].w * inv;
        o.x = o.x > 0.f ? o.x : expm1f(o.x);
        o.y = o.y > 0.f ? o.y : expm1f(o.y);
        o.z = o.z > 0.f ? o.z : expm1f(o.z);
        o.w = o.w > 0.f ? o.w : expm1f(o.w);
        __half2 ha = __floats2half2_rn(o.x, o.y);
        __half2 hb = __floats2half2_rn(o.z, o.w);
        uint2 u;
        u.x = *(unsigned int*)&ha;
        u.y = *(unsigned int*)&hb;
        __stcs((uint2*)(outp + k * 128 + lane * 4), u);
    }
}

// ---------------- layer-2 aggregation + softmax: warp per node (fp16 h2) ----------------
__global__ void agg2_kernel(float* __restrict__ out) {
    int node = (blockIdx.x * blockDim.x + threadIdx.x) >> 5;
    if (node >= Nn) return;
    int lane = threadIdx.x & 31;

    float ss = g_ssrc2[node];
    int beg = g_rowptr[node], end = g_rowptr[node + 1];
    float a0 = 0.f, a1 = 0.f, rs = 0.f;
    for (int j = beg; j < end; j++) {
        int d = g_dst[j];
        float sc = ss + g_sdst2[d];
        float lr = sc > 0.f ? sc : ALPHA * sc;
        float w = __expf(-lr);
        const __half2* hp = (const __half2*)(g_h2h + (size_t)d * OUTF);
        unsigned int uu = __ldcg((const unsigned int*)(hp + lane));
        float2 f = __half22float2(*(__half2*)&uu);
        a0 += w * f.x;
        a1 += w * f.y;
        rs += w;
    }
    float inv = 1.f / (rs + 1e-16f);
    float v0 = a0 * inv, v1 = a1 * inv;

    float m = fmaxf(v0, v1);
    #pragma unroll
    for (int off = 16; off; off >>= 1) m = fmaxf(m, __shfl_xor_sync(0xffffffffu, m, off));
    float e0 = __expf(v0 - m), e1 = __expf(v1 - m);
    float s = e0 + e1;
    #pragma unroll
    for (int off = 16; off; off >>= 1) s += __shfl_xor_sync(0xffffffffu, s, off);
    float invs = 1.f / s;
    *(float2*)(out + (size_t)node * OUTF + lane * 2) = make_float2(e0 * invs, e1 * invs);
}

// ---------------- launch ----------------
extern "C" void kernel_launch(void* const* d_in, const int* in_sizes, int n_in,
                              void* d_out, int out_size) {
    const float* x       = (const float*)d_in[0];
    const int*   edges   = (const int*)  d_in[1];
    const float* W0      = (const float*)d_in[2];
    const float* b0      = (const float*)d_in[3];
    const float* W_heads = (const float*)d_in[4];
    const float* a_heads = (const float*)d_in[5];
    const float* W_end   = (const float*)d_in[6];
    const float* a_end   = (const float*)d_in[7];
    float* out = (float*)d_out;
    const int* src = edges;
    const int* dst = edges + Ee;

    __half *p_h1, *p_out1, *p_h2h, *p_W0h, *p_Wcath, *p_Wendh;
    float  *p_ssrc1, *p_sdst1, *p_ssrc2, *p_sdst2;
    cudaGetSymbolAddress((void**)&p_h1,    g_h1);
    cudaGetSymbolAddress((void**)&p_out1,  g_out1);
    cudaGetSymbolAddress((void**)&p_h2h,   g_h2h);
    cudaGetSymbolAddress((void**)&p_W0h,   g_W0h);
    cudaGetSymbolAddress((void**)&p_Wcath, g_Wcat_h);
    cudaGetSymbolAddress((void**)&p_Wendh, g_Wend_h);
    cudaGetSymbolAddress((void**)&p_ssrc1, g_ssrc1);
    cudaGetSymbolAddress((void**)&p_sdst1, g_sdst1);
    cudaGetSymbolAddress((void**)&p_ssrc2, g_ssrc2);
    cudaGetSymbolAddress((void**)&p_sdst2, g_sdst2);

    // Side stream + fork/join events (host-side objects only; created once).
    static cudaStream_t s_csr = nullptr;
    static cudaEvent_t  ev_fork = nullptr, ev_join = nullptr;
    if (s_csr == nullptr) {
        cudaStreamCreateWithFlags(&s_csr, cudaStreamNonBlocking);
        cudaEventCreateWithFlags(&ev_fork, cudaEventDisableTiming);
        cudaEventCreateWithFlags(&ev_join, cudaEventDisableTiming);
    }

    // ---- fork: CSR chain on side stream ----
    cudaEventRecord(ev_fork, 0);
    cudaStreamWaitEvent(s_csr, ev_fork, 0);
    zero_counts_kernel<<<(Nn + 255) / 256, 256, 0, s_csr>>>();
    count_kernel<<<(Ee + 255) / 256, 256, 0, s_csr>>>(src);
    scan_block_kernel<<<NB_SCAN, 1024, 0, s_csr>>>();
    scan_top_kernel<<<1, 128, 0, s_csr>>>();
    scan_add_kernel<<<(Nn + 255) / 256, 256, 0, s_csr>>>();
    scatter_kernel<<<(Ee + 255) / 256, 256, 0, s_csr>>>(src, dst);
    cudaEventRecord(ev_join, s_csr);

    // ---- main stream: dense chain (independent of CSR until agg1) ----
    prep_kernel<<<(Nn * NH + 255) / 256, 256>>>(W0, W_end, W_heads);

    const int GY = (Nn + 127) / 128;   // 782

    // FUSED: xp = x@W0+b0 (x converted fp32->fp16 in-register, smem-resident);
    //        h1 = xp@Wcat + fused s1 scores
    fused_g12_kernel<<<GY, 256>>>(x, p_W0h, b0, p_Wcath, a_heads,
                                  p_h1, p_ssrc1, p_sdst1, Nn);

    // ---- join: agg1 needs both the CSR and the dense chain ----
    cudaStreamWaitEvent(0, ev_join, 0);

    // layer-1 aggregation + ELU -> out1 [N,512] (fp16)
    agg1_kernel<<<(Nn + 7) / 8, 256>>>();
    // h2 = out1 @ W_end  (fp16 out; A read-once -> streaming) + fused s2 scores
    mma_gemm_kernel<true, false, true, true><<<dim3(OUTF / 64, GY), 256>>>(
        p_out1, p_Wendh, nullptr, p_h2h, a_end, p_ssrc2, p_sdst2, 1, Nn, F1, OUTF);
    // layer-2 aggregation + softmax -> output
    agg2_kernel<<<(Nn + 7) / 8, 256>>>(out);
}